// round 5
// baseline (speedup 1.0000x reference)
#include <cuda_runtime.h>
#include <cuda_bf16.h>
#include <math.h>
#include <stdint.h>

// Problem constants
#define BATCH 2
#define SEQ   2048
#define DIM   1024
#define HEADS 16
#define DH    64
#define MTOT  (BATCH*SEQ)          // 4096 rows

// Scratch (allocation-free rule: __device__ globals)
__device__ float g_qkv[(size_t)MTOT * 3 * DIM];   // [4096, 3072]
__device__ float g_attn[(size_t)MTOT * DIM];      // [4096, 1024]

__device__ __forceinline__ uint32_t f2tf32(float v) {
    uint32_t o;
    asm("cvt.rna.tf32.f32 %0, %1;" : "=r"(o) : "f"(v));
    return o;
}

__device__ __forceinline__ void mma_tf32(float c[4], const uint32_t a[4], const uint32_t b[2]) {
    asm volatile(
        "mma.sync.aligned.m16n8k8.row.col.f32.tf32.tf32.f32 "
        "{%0,%1,%2,%3}, {%4,%5,%6,%7}, {%8,%9}, {%0,%1,%2,%3};"
        : "+f"(c[0]), "+f"(c[1]), "+f"(c[2]), "+f"(c[3])
        : "r"(a[0]), "r"(a[1]), "r"(a[2]), "r"(a[3]), "r"(b[0]), "r"(b[1]));
}

// ---------------------------------------------------------------------------
// TF32 tensor-core GEMM (unchanged from R1): C = A @ B, row-major fp32.
// ---------------------------------------------------------------------------
#define GBM 128
#define GBN 128
#define GBK 16
#define GSTRIDE 20

__global__ __launch_bounds__(256) void sgemm_tf32(const float* __restrict__ A,
                                                  const float* __restrict__ B,
                                                  float* __restrict__ C,
                                                  int M, int N, int K) {
    __shared__ uint32_t As[2][GBM][GSTRIDE];
    __shared__ uint32_t Bs[2][GBN][GSTRIDE];

    const int tid  = threadIdx.x;
    const int lane = tid & 31;
    const int wid  = tid >> 5;
    const int wm   = wid & 3;
    const int wn   = wid >> 2;
    const int g    = lane >> 2;
    const int q    = lane & 3;

    const int m0 = blockIdx.y * GBM;
    const int n0 = blockIdx.x * GBN;

    const int a_row  = tid >> 2;
    const int a_col4 = (tid & 3) * 4;
    const int b_k    = tid >> 4;
    const int b_n4   = (tid & 15) * 4;

    float acc[2][8][4];
#pragma unroll
    for (int i = 0; i < 2; i++)
#pragma unroll
        for (int j = 0; j < 8; j++)
#pragma unroll
            for (int r = 0; r < 4; r++) acc[i][j][r] = 0.f;

    const int ntiles = K / GBK;

    float4 ra[2], rb[2];
#pragma unroll
    for (int i = 0; i < 2; i++) {
        ra[i] = *(const float4*)&A[(size_t)(m0 + a_row + 64 * i) * K + a_col4];
        rb[i] = *(const float4*)&B[(size_t)b_k * N + n0 + b_n4 + 64 * i];
    }
#pragma unroll
    for (int i = 0; i < 2; i++) {
        int r = a_row + 64 * i;
        As[0][r][a_col4 + 0] = f2tf32(ra[i].x);
        As[0][r][a_col4 + 1] = f2tf32(ra[i].y);
        As[0][r][a_col4 + 2] = f2tf32(ra[i].z);
        As[0][r][a_col4 + 3] = f2tf32(ra[i].w);
        int n = b_n4 + 64 * i;
        Bs[0][n + 0][b_k] = f2tf32(rb[i].x);
        Bs[0][n + 1][b_k] = f2tf32(rb[i].y);
        Bs[0][n + 2][b_k] = f2tf32(rb[i].z);
        Bs[0][n + 3][b_k] = f2tf32(rb[i].w);
    }
    __syncthreads();

    for (int kt = 0; kt < ntiles; kt++) {
        const int cur = kt & 1, nxt = cur ^ 1;
        const bool more = (kt + 1 < ntiles);

        if (more) {
            int k0 = (kt + 1) * GBK;
#pragma unroll
            for (int i = 0; i < 2; i++) {
                ra[i] = *(const float4*)&A[(size_t)(m0 + a_row + 64 * i) * K + k0 + a_col4];
                rb[i] = *(const float4*)&B[(size_t)(k0 + b_k) * N + n0 + b_n4 + 64 * i];
            }
        }

#pragma unroll
        for (int ks = 0; ks < 2; ks++) {
            uint32_t afr[2][4];
#pragma unroll
            for (int mt = 0; mt < 2; mt++) {
                int rb0 = wm * 32 + mt * 16;
                afr[mt][0] = As[cur][rb0 + g][ks * 8 + q];
                afr[mt][1] = As[cur][rb0 + g + 8][ks * 8 + q];
                afr[mt][2] = As[cur][rb0 + g][ks * 8 + q + 4];
                afr[mt][3] = As[cur][rb0 + g + 8][ks * 8 + q + 4];
            }
#pragma unroll
            for (int nt = 0; nt < 8; nt++) {
                int nb = wn * 64 + nt * 8;
                uint32_t bfr[2];
                bfr[0] = Bs[cur][nb + g][ks * 8 + q];
                bfr[1] = Bs[cur][nb + g][ks * 8 + q + 4];
                mma_tf32(acc[0][nt], afr[0], bfr);
                mma_tf32(acc[1][nt], afr[1], bfr);
            }
        }

        if (more) {
#pragma unroll
            for (int i = 0; i < 2; i++) {
                int r = a_row + 64 * i;
                As[nxt][r][a_col4 + 0] = f2tf32(ra[i].x);
                As[nxt][r][a_col4 + 1] = f2tf32(ra[i].y);
                As[nxt][r][a_col4 + 2] = f2tf32(ra[i].z);
                As[nxt][r][a_col4 + 3] = f2tf32(ra[i].w);
                int n = b_n4 + 64 * i;
                Bs[nxt][n + 0][b_k] = f2tf32(rb[i].x);
                Bs[nxt][n + 1][b_k] = f2tf32(rb[i].y);
                Bs[nxt][n + 2][b_k] = f2tf32(rb[i].z);
                Bs[nxt][n + 3][b_k] = f2tf32(rb[i].w);
            }
        }
        __syncthreads();
    }

#pragma unroll
    for (int mt = 0; mt < 2; mt++) {
        int r0 = m0 + wm * 32 + mt * 16 + g;
#pragma unroll
        for (int nt = 0; nt < 8; nt++) {
            int c0 = n0 + wn * 64 + nt * 8 + q * 2;
            *(float2*)&C[(size_t)r0 * N + c0]       = make_float2(acc[mt][nt][0], acc[mt][nt][1]);
            *(float2*)&C[(size_t)(r0 + 8) * N + c0] = make_float2(acc[mt][nt][2], acc[mt][nt][3]);
        }
    }
}

// ---------------------------------------------------------------------------
// Flash attention with TF32 mma.sync tensor cores.
// Block: 128 threads (4 warps) handles the q-tile PAIR {qi, 15-qi} for one
// (b,h) -> perfectly balanced causal work (34 key-tiles per block).
// Each warp: 32 q-rows x 64 keys. Softmax in mma C-fragment layout, base-2.
// Smem: Qs[128][68] tf32, Ks[64][68] (key-major), Vs[64][68] (d-major,
// i.e. V transposed), Ps[4][32][68] per-warp P tiles.
// ---------------------------------------------------------------------------
#define FSTR 68
#define NQT  (SEQ/128)   // 16 q-tiles
#define FLASH_SMEM ((128*FSTR + 64*FSTR + 64*FSTR + 4*32*FSTR) * 4)

__global__ __launch_bounds__(128) void flash_mma(const float* __restrict__ qkv,
                                                 float* __restrict__ attn_out) {
    extern __shared__ uint32_t sm[];
    uint32_t* Qs = sm;                       // [qrow][d]
    uint32_t* Ks = Qs + 128 * FSTR;          // [key][d]
    uint32_t* Vs = Ks + 64 * FSTR;           // [d][key]  (V^T)
    uint32_t* Ps = Vs + 64 * FSTR;           // [warp][row][key]

    const int tid  = threadIdx.x;
    const int lane = tid & 31;
    const int w    = tid >> 5;
    const int g    = lane >> 2;
    const int q    = lane & 3;

    const int bh = blockIdx.y;
    const int b  = bh >> 4;
    const int h  = bh & 15;

    const float LOG2E  = 1.44269504088896f;
    const float scale2 = 0.125f * LOG2E;                       // Dh^-0.5 * log2(e)
    const float slope2 = exp2f(-0.5f * (float)(h + 1)) * LOG2E;

    const float* qb = qkv + (size_t)b * SEQ * (3 * DIM) + h * DH;
    const float* kb = qb + DIM;
    const float* vb = qb + 2 * DIM;

    uint32_t* Pw = Ps + w * 32 * FSTR;

#pragma unroll 1
    for (int half = 0; half < 2; half++) {
        const int qi = half ? (NQT - 1 - blockIdx.x) : blockIdx.x;
        const int q0 = qi * 128;

        __syncthreads();   // Qs/Ks/Vs reuse across halves

        // ---- load Q tile (rows q0..q0+127) as tf32, [row][d] ----
        {
            int r  = tid >> 4;
            int d4 = (tid & 15) * 4;
#pragma unroll
            for (int it = 0; it < 16; it++, r += 8) {
                float4 v = *(const float4*)&qb[(size_t)(q0 + r) * (3 * DIM) + d4];
                *(uint4*)&Qs[r * FSTR + d4] =
                    make_uint4(f2tf32(v.x), f2tf32(v.y), f2tf32(v.z), f2tf32(v.w));
            }
        }

        // per-row state (rows: mt*16+g and mt*16+g+8 within warp tile)
        float o[2][8][4];
        float mprev[2][2], lrun[2][2];
#pragma unroll
        for (int mt = 0; mt < 2; mt++) {
            mprev[mt][0] = mprev[mt][1] = -1e30f;
            lrun[mt][0]  = lrun[mt][1]  = 0.f;
#pragma unroll
            for (int nt = 0; nt < 8; nt++)
#pragma unroll
                for (int r = 0; r < 4; r++) o[mt][nt][r] = 0.f;
        }

        const int nkt = 2 * qi + 2;
        const int wrow_min = q0 + w * 32;       // warp's first q-row
        const int wrow_max = wrow_min + 31;

        for (int kt = 0; kt < nkt; kt++) {
            const int k0 = kt * 64;
            __syncthreads();   // previous tile's PV reads done

            // ---- load K [key][d] and V^T [d][key] ----
            {
                int key = tid >> 4;
                int d4  = (tid & 15) * 4;
#pragma unroll
                for (int it = 0; it < 8; it++, key += 8) {
                    float4 kv = *(const float4*)&kb[(size_t)(k0 + key) * (3 * DIM) + d4];
                    *(uint4*)&Ks[key * FSTR + d4] =
                        make_uint4(f2tf32(kv.x), f2tf32(kv.y), f2tf32(kv.z), f2tf32(kv.w));
                    float4 vv = *(const float4*)&vb[(size_t)(k0 + key) * (3 * DIM) + d4];
                    Vs[(d4 + 0) * FSTR + key] = f2tf32(vv.x);
                    Vs[(d4 + 1) * FSTR + key] = f2tf32(vv.y);
                    Vs[(d4 + 2) * FSTR + key] = f2tf32(vv.z);
                    Vs[(d4 + 3) * FSTR + key] = f2tf32(vv.w);
                }
            }
            __syncthreads();

            // warp-uniform skip: entire tile above the diagonal for this warp
            if (k0 > wrow_max) continue;

            // ---- S = Q @ K^T ----
            float s[2][8][4];
#pragma unroll
            for (int mt = 0; mt < 2; mt++)
#pragma unroll
                for (int nt = 0; nt < 8; nt++)
#pragma unroll
                    for (int r = 0; r < 4; r++) s[mt][nt][r] = 0.f;

#pragma unroll
            for (int ks = 0; ks < 8; ks++) {
                uint32_t afr[2][4];
#pragma unroll
                for (int mt = 0; mt < 2; mt++) {
                    int rb0 = w * 32 + mt * 16;
                    afr[mt][0] = Qs[(rb0 + g)     * FSTR + ks * 8 + q];
                    afr[mt][1] = Qs[(rb0 + g + 8) * FSTR + ks * 8 + q];
                    afr[mt][2] = Qs[(rb0 + g)     * FSTR + ks * 8 + q + 4];
                    afr[mt][3] = Qs[(rb0 + g + 8) * FSTR + ks * 8 + q + 4];
                }
#pragma unroll
                for (int nt = 0; nt < 8; nt++) {
                    uint32_t bfr[2];
                    bfr[0] = Ks[(nt * 8 + g) * FSTR + ks * 8 + q];
                    bfr[1] = Ks[(nt * 8 + g) * FSTR + ks * 8 + q + 4];
                    mma_tf32(s[0][nt], afr[0], bfr);
                    mma_tf32(s[1][nt], afr[1], bfr);
                }
            }

            // ---- bias + mask + online softmax (base-2 domain) ----
            const bool need_mask = (k0 + 63 > wrow_min);
#pragma unroll
            for (int mt = 0; mt < 2; mt++) {
                const int r0 = wrow_min + mt * 16 + g;
                const int r1 = r0 + 8;
                float mx0 = -1e30f, mx1 = -1e30f;
#pragma unroll
                for (int nt = 0; nt < 8; nt++) {
#pragma unroll
                    for (int jj = 0; jj < 2; jj++) {
                        int col = k0 + nt * 8 + q * 2 + jj;
                        float bias = slope2 * (float)col;
                        float v0 = fmaf(s[mt][nt][jj],     scale2, bias);
                        float v1 = fmaf(s[mt][nt][2 + jj], scale2, bias);
                        if (need_mask) {
                            if (col > r0) v0 = -1e30f;
                            if (col > r1) v1 = -1e30f;
                        }
                        s[mt][nt][jj]     = v0;
                        s[mt][nt][2 + jj] = v1;
                        mx0 = fmaxf(mx0, v0);
                        mx1 = fmaxf(mx1, v1);
                    }
                }
                mx0 = fmaxf(mx0, __shfl_xor_sync(0xffffffffu, mx0, 1));
                mx0 = fmaxf(mx0, __shfl_xor_sync(0xffffffffu, mx0, 2));
                mx1 = fmaxf(mx1, __shfl_xor_sync(0xffffffffu, mx1, 1));
                mx1 = fmaxf(mx1, __shfl_xor_sync(0xffffffffu, mx1, 2));

                float mn0 = fmaxf(mprev[mt][0], mx0);
                float mn1 = fmaxf(mprev[mt][1], mx1);
                float sum0 = 0.f, sum1 = 0.f;
#pragma unroll
                for (int nt = 0; nt < 8; nt++) {
#pragma unroll
                    for (int jj = 0; jj < 2; jj++) {
                        float p0 = exp2f(s[mt][nt][jj]     - mn0);
                        float p1 = exp2f(s[mt][nt][2 + jj] - mn1);
                        s[mt][nt][jj]     = p0;
                        s[mt][nt][2 + jj] = p1;
                        sum0 += p0;
                        sum1 += p1;
                    }
                }
                sum0 += __shfl_xor_sync(0xffffffffu, sum0, 1);
                sum0 += __shfl_xor_sync(0xffffffffu, sum0, 2);
                sum1 += __shfl_xor_sync(0xffffffffu, sum1, 1);
                sum1 += __shfl_xor_sync(0xffffffffu, sum1, 2);

                float al0 = exp2f(mprev[mt][0] - mn0);
                float al1 = exp2f(mprev[mt][1] - mn1);
                lrun[mt][0] = lrun[mt][0] * al0 + sum0;
                lrun[mt][1] = lrun[mt][1] * al1 + sum1;
                mprev[mt][0] = mn0;
                mprev[mt][1] = mn1;
#pragma unroll
                for (int nt = 0; nt < 8; nt++) {
                    o[mt][nt][0] *= al0;
                    o[mt][nt][1] *= al0;
                    o[mt][nt][2] *= al1;
                    o[mt][nt][3] *= al1;
                }

                // write P tile (per-warp private smem), tf32, STS.64 pairs
#pragma unroll
                for (int nt = 0; nt < 8; nt++) {
                    *(uint2*)&Pw[(mt * 16 + g)     * FSTR + nt * 8 + q * 2] =
                        make_uint2(f2tf32(s[mt][nt][0]), f2tf32(s[mt][nt][1]));
                    *(uint2*)&Pw[(mt * 16 + g + 8) * FSTR + nt * 8 + q * 2] =
                        make_uint2(f2tf32(s[mt][nt][2]), f2tf32(s[mt][nt][3]));
                }
            }
            __syncwarp();

            // ---- O += P @ V ----
#pragma unroll
            for (int ks = 0; ks < 8; ks++) {
                uint32_t afr[2][4];
#pragma unroll
                for (int mt = 0; mt < 2; mt++) {
                    afr[mt][0] = Pw[(mt * 16 + g)     * FSTR + ks * 8 + q];
                    afr[mt][1] = Pw[(mt * 16 + g + 8) * FSTR + ks * 8 + q];
                    afr[mt][2] = Pw[(mt * 16 + g)     * FSTR + ks * 8 + q + 4];
                    afr[mt][3] = Pw[(mt * 16 + g + 8) * FSTR + ks * 8 + q + 4];
                }
#pragma unroll
                for (int nt = 0; nt < 8; nt++) {
                    uint32_t bfr[2];
                    bfr[0] = Vs[(nt * 8 + g) * FSTR + ks * 8 + q];
                    bfr[1] = Vs[(nt * 8 + g) * FSTR + ks * 8 + q + 4];
                    mma_tf32(o[0][nt], afr[0], bfr);
                    mma_tf32(o[1][nt], afr[1], bfr);
                }
            }
        }

        // ---- epilogue: normalize, store [b, row, h*64 + d] ----
#pragma unroll
        for (int mt = 0; mt < 2; mt++) {
            float inv0 = 1.f / lrun[mt][0];
            float inv1 = 1.f / lrun[mt][1];
            int r0 = q0 + w * 32 + mt * 16 + g;
#pragma unroll
            for (int nt = 0; nt < 8; nt++) {
                int c = h * DH + nt * 8 + q * 2;
                *(float2*)&attn_out[(size_t)(b * SEQ + r0) * DIM + c] =
                    make_float2(o[mt][nt][0] * inv0, o[mt][nt][1] * inv0);
                *(float2*)&attn_out[(size_t)(b * SEQ + r0 + 8) * DIM + c] =
                    make_float2(o[mt][nt][2] * inv1, o[mt][nt][3] * inv1);
            }
        }
    }
}

// ---------------------------------------------------------------------------
extern "C" void kernel_launch(void* const* d_in, const int* in_sizes, int n_in,
                              void* d_out, int out_size) {
    const float* x      = (const float*)d_in[0];   // [2,2048,1024]
    const float* w_qkv  = (const float*)d_in[1];   // [1024,3072]
    const float* w_proj = (const float*)d_in[2];   // [1024,1024]
    float* out = (float*)d_out;                    // [2,2048,1024]

    float *qkv_ptr, *attn_ptr;
    cudaGetSymbolAddress((void**)&qkv_ptr, g_qkv);
    cudaGetSymbolAddress((void**)&attn_ptr, g_attn);

    cudaFuncSetAttribute(flash_mma, cudaFuncAttributeMaxDynamicSharedMemorySize,
                         (int)FLASH_SMEM);

    // 1) qkv = x @ w_qkv    [4096,1024]@[1024,3072]
    sgemm_tf32<<<dim3(3 * DIM / GBN, MTOT / GBM), 256>>>(x, w_qkv, qkv_ptr, MTOT, 3 * DIM, DIM);

    // 2) attention (balanced q-tile pairs)
    flash_mma<<<dim3(NQT / 2, BATCH * HEADS), 128, FLASH_SMEM>>>(qkv_ptr, attn_ptr);

    // 3) out = attn @ w_proj [4096,1024]@[1024,1024]
    sgemm_tf32<<<dim3(DIM / GBN, MTOT / GBM), 256>>>(attn_ptr, w_proj, out, MTOT, DIM, DIM);
}

// round 6
// speedup vs baseline: 1.0017x; 1.0017x over previous
#include <cuda_runtime.h>
#include <cuda_bf16.h>
#include <math.h>
#include <stdint.h>

// Problem constants
#define BATCH 2
#define SEQ   2048
#define DIM   1024
#define HEADS 16
#define DH    64
#define MTOT  (BATCH*SEQ)          // 4096 rows

// Scratch (allocation-free rule: __device__ globals)
__device__ float g_qkv[(size_t)MTOT * 3 * DIM];   // [4096, 3072]
__device__ float g_attn[(size_t)MTOT * DIM];      // [4096, 1024]

__device__ __forceinline__ uint32_t f2tf32(float v) {
    uint32_t o;
    asm("cvt.rna.tf32.f32 %0, %1;" : "=r"(o) : "f"(v));
    return o;
}

__device__ __forceinline__ void mma_tf32(float c[4], const uint32_t a[4], const uint32_t b[2]) {
    asm volatile(
        "mma.sync.aligned.m16n8k8.row.col.f32.tf32.tf32.f32 "
        "{%0,%1,%2,%3}, {%4,%5,%6,%7}, {%8,%9}, {%0,%1,%2,%3};"
        : "+f"(c[0]), "+f"(c[1]), "+f"(c[2]), "+f"(c[3])
        : "r"(a[0]), "r"(a[1]), "r"(a[2]), "r"(a[3]), "r"(b[0]), "r"(b[1]));
}

// ---------------------------------------------------------------------------
// TF32 tensor-core GEMM (unchanged from R1): C = A @ B, row-major fp32.
// ---------------------------------------------------------------------------
#define GBM 128
#define GBN 128
#define GBK 16
#define GSTRIDE 20

__global__ __launch_bounds__(256) void sgemm_tf32(const float* __restrict__ A,
                                                  const float* __restrict__ B,
                                                  float* __restrict__ C,
                                                  int M, int N, int K) {
    __shared__ uint32_t As[2][GBM][GSTRIDE];
    __shared__ uint32_t Bs[2][GBN][GSTRIDE];

    const int tid  = threadIdx.x;
    const int lane = tid & 31;
    const int wid  = tid >> 5;
    const int wm   = wid & 3;
    const int wn   = wid >> 2;
    const int g    = lane >> 2;
    const int q    = lane & 3;

    const int m0 = blockIdx.y * GBM;
    const int n0 = blockIdx.x * GBN;

    const int a_row  = tid >> 2;
    const int a_col4 = (tid & 3) * 4;
    const int b_k    = tid >> 4;
    const int b_n4   = (tid & 15) * 4;

    float acc[2][8][4];
#pragma unroll
    for (int i = 0; i < 2; i++)
#pragma unroll
        for (int j = 0; j < 8; j++)
#pragma unroll
            for (int r = 0; r < 4; r++) acc[i][j][r] = 0.f;

    const int ntiles = K / GBK;

    float4 ra[2], rb[2];
#pragma unroll
    for (int i = 0; i < 2; i++) {
        ra[i] = *(const float4*)&A[(size_t)(m0 + a_row + 64 * i) * K + a_col4];
        rb[i] = *(const float4*)&B[(size_t)b_k * N + n0 + b_n4 + 64 * i];
    }
#pragma unroll
    for (int i = 0; i < 2; i++) {
        int r = a_row + 64 * i;
        As[0][r][a_col4 + 0] = f2tf32(ra[i].x);
        As[0][r][a_col4 + 1] = f2tf32(ra[i].y);
        As[0][r][a_col4 + 2] = f2tf32(ra[i].z);
        As[0][r][a_col4 + 3] = f2tf32(ra[i].w);
        int n = b_n4 + 64 * i;
        Bs[0][n + 0][b_k] = f2tf32(rb[i].x);
        Bs[0][n + 1][b_k] = f2tf32(rb[i].y);
        Bs[0][n + 2][b_k] = f2tf32(rb[i].z);
        Bs[0][n + 3][b_k] = f2tf32(rb[i].w);
    }
    __syncthreads();

    for (int kt = 0; kt < ntiles; kt++) {
        const int cur = kt & 1, nxt = cur ^ 1;
        const bool more = (kt + 1 < ntiles);

        if (more) {
            int k0 = (kt + 1) * GBK;
#pragma unroll
            for (int i = 0; i < 2; i++) {
                ra[i] = *(const float4*)&A[(size_t)(m0 + a_row + 64 * i) * K + k0 + a_col4];
                rb[i] = *(const float4*)&B[(size_t)(k0 + b_k) * N + n0 + b_n4 + 64 * i];
            }
        }

#pragma unroll
        for (int ks = 0; ks < 2; ks++) {
            uint32_t afr[2][4];
#pragma unroll
            for (int mt = 0; mt < 2; mt++) {
                int rb0 = wm * 32 + mt * 16;
                afr[mt][0] = As[cur][rb0 + g][ks * 8 + q];
                afr[mt][1] = As[cur][rb0 + g + 8][ks * 8 + q];
                afr[mt][2] = As[cur][rb0 + g][ks * 8 + q + 4];
                afr[mt][3] = As[cur][rb0 + g + 8][ks * 8 + q + 4];
            }
#pragma unroll
            for (int nt = 0; nt < 8; nt++) {
                int nb = wn * 64 + nt * 8;
                uint32_t bfr[2];
                bfr[0] = Bs[cur][nb + g][ks * 8 + q];
                bfr[1] = Bs[cur][nb + g][ks * 8 + q + 4];
                mma_tf32(acc[0][nt], afr[0], bfr);
                mma_tf32(acc[1][nt], afr[1], bfr);
            }
        }

        if (more) {
#pragma unroll
            for (int i = 0; i < 2; i++) {
                int r = a_row + 64 * i;
                As[nxt][r][a_col4 + 0] = f2tf32(ra[i].x);
                As[nxt][r][a_col4 + 1] = f2tf32(ra[i].y);
                As[nxt][r][a_col4 + 2] = f2tf32(ra[i].z);
                As[nxt][r][a_col4 + 3] = f2tf32(ra[i].w);
                int n = b_n4 + 64 * i;
                Bs[nxt][n + 0][b_k] = f2tf32(rb[i].x);
                Bs[nxt][n + 1][b_k] = f2tf32(rb[i].y);
                Bs[nxt][n + 2][b_k] = f2tf32(rb[i].z);
                Bs[nxt][n + 3][b_k] = f2tf32(rb[i].w);
            }
        }
        __syncthreads();
    }

#pragma unroll
    for (int mt = 0; mt < 2; mt++) {
        int r0 = m0 + wm * 32 + mt * 16 + g;
#pragma unroll
        for (int nt = 0; nt < 8; nt++) {
            int c0 = n0 + wn * 64 + nt * 8 + q * 2;
            *(float2*)&C[(size_t)r0 * N + c0]       = make_float2(acc[mt][nt][0], acc[mt][nt][1]);
            *(float2*)&C[(size_t)(r0 + 8) * N + c0] = make_float2(acc[mt][nt][2], acc[mt][nt][3]);
        }
    }
}

// ---------------------------------------------------------------------------
// Flash attention with TF32 mma.sync tensor cores.
// Block: 128 threads (4 warps) handles the q-tile PAIR {qi, 15-qi} for one
// (b,h) -> perfectly balanced causal work (34 key-tiles per block).
// Each warp: 32 q-rows x 64 keys. Softmax in mma C-fragment layout, base-2.
// Smem: Qs[128][68] tf32, Ks[64][68] (key-major), Vs[64][68] (d-major,
// i.e. V transposed), Ps[4][32][68] per-warp P tiles.
// ---------------------------------------------------------------------------
#define FSTR 68
#define NQT  (SEQ/128)   // 16 q-tiles
#define FLASH_SMEM ((128*FSTR + 64*FSTR + 64*FSTR + 4*32*FSTR) * 4)

__global__ __launch_bounds__(128) void flash_mma(const float* __restrict__ qkv,
                                                 float* __restrict__ attn_out) {
    extern __shared__ uint32_t sm[];
    uint32_t* Qs = sm;                       // [qrow][d]
    uint32_t* Ks = Qs + 128 * FSTR;          // [key][d]
    uint32_t* Vs = Ks + 64 * FSTR;           // [d][key]  (V^T)
    uint32_t* Ps = Vs + 64 * FSTR;           // [warp][row][key]

    const int tid  = threadIdx.x;
    const int lane = tid & 31;
    const int w    = tid >> 5;
    const int g    = lane >> 2;
    const int q    = lane & 3;

    const int bh = blockIdx.y;
    const int b  = bh >> 4;
    const int h  = bh & 15;

    const float LOG2E  = 1.44269504088896f;
    const float scale2 = 0.125f * LOG2E;                       // Dh^-0.5 * log2(e)
    const float slope2 = exp2f(-0.5f * (float)(h + 1)) * LOG2E;

    const float* qb = qkv + (size_t)b * SEQ * (3 * DIM) + h * DH;
    const float* kb = qb + DIM;
    const float* vb = qb + 2 * DIM;

    uint32_t* Pw = Ps + w * 32 * FSTR;

#pragma unroll 1
    for (int half = 0; half < 2; half++) {
        const int qi = half ? (NQT - 1 - blockIdx.x) : blockIdx.x;
        const int q0 = qi * 128;

        __syncthreads();   // Qs/Ks/Vs reuse across halves

        // ---- load Q tile (rows q0..q0+127) as tf32, [row][d] ----
        {
            int r  = tid >> 4;
            int d4 = (tid & 15) * 4;
#pragma unroll
            for (int it = 0; it < 16; it++, r += 8) {
                float4 v = *(const float4*)&qb[(size_t)(q0 + r) * (3 * DIM) + d4];
                *(uint4*)&Qs[r * FSTR + d4] =
                    make_uint4(f2tf32(v.x), f2tf32(v.y), f2tf32(v.z), f2tf32(v.w));
            }
        }

        // per-row state (rows: mt*16+g and mt*16+g+8 within warp tile)
        float o[2][8][4];
        float mprev[2][2], lrun[2][2];
#pragma unroll
        for (int mt = 0; mt < 2; mt++) {
            mprev[mt][0] = mprev[mt][1] = -1e30f;
            lrun[mt][0]  = lrun[mt][1]  = 0.f;
#pragma unroll
            for (int nt = 0; nt < 8; nt++)
#pragma unroll
                for (int r = 0; r < 4; r++) o[mt][nt][r] = 0.f;
        }

        const int nkt = 2 * qi + 2;
        const int wrow_min = q0 + w * 32;       // warp's first q-row
        const int wrow_max = wrow_min + 31;

        for (int kt = 0; kt < nkt; kt++) {
            const int k0 = kt * 64;
            __syncthreads();   // previous tile's PV reads done

            // ---- load K [key][d] and V^T [d][key] ----
            {
                int key = tid >> 4;
                int d4  = (tid & 15) * 4;
#pragma unroll
                for (int it = 0; it < 8; it++, key += 8) {
                    float4 kv = *(const float4*)&kb[(size_t)(k0 + key) * (3 * DIM) + d4];
                    *(uint4*)&Ks[key * FSTR + d4] =
                        make_uint4(f2tf32(kv.x), f2tf32(kv.y), f2tf32(kv.z), f2tf32(kv.w));
                    float4 vv = *(const float4*)&vb[(size_t)(k0 + key) * (3 * DIM) + d4];
                    Vs[(d4 + 0) * FSTR + key] = f2tf32(vv.x);
                    Vs[(d4 + 1) * FSTR + key] = f2tf32(vv.y);
                    Vs[(d4 + 2) * FSTR + key] = f2tf32(vv.z);
                    Vs[(d4 + 3) * FSTR + key] = f2tf32(vv.w);
                }
            }
            __syncthreads();

            // warp-uniform skip: entire tile above the diagonal for this warp
            if (k0 > wrow_max) continue;

            // ---- S = Q @ K^T ----
            float s[2][8][4];
#pragma unroll
            for (int mt = 0; mt < 2; mt++)
#pragma unroll
                for (int nt = 0; nt < 8; nt++)
#pragma unroll
                    for (int r = 0; r < 4; r++) s[mt][nt][r] = 0.f;

#pragma unroll
            for (int ks = 0; ks < 8; ks++) {
                uint32_t afr[2][4];
#pragma unroll
                for (int mt = 0; mt < 2; mt++) {
                    int rb0 = w * 32 + mt * 16;
                    afr[mt][0] = Qs[(rb0 + g)     * FSTR + ks * 8 + q];
                    afr[mt][1] = Qs[(rb0 + g + 8) * FSTR + ks * 8 + q];
                    afr[mt][2] = Qs[(rb0 + g)     * FSTR + ks * 8 + q + 4];
                    afr[mt][3] = Qs[(rb0 + g + 8) * FSTR + ks * 8 + q + 4];
                }
#pragma unroll
                for (int nt = 0; nt < 8; nt++) {
                    uint32_t bfr[2];
                    bfr[0] = Ks[(nt * 8 + g) * FSTR + ks * 8 + q];
                    bfr[1] = Ks[(nt * 8 + g) * FSTR + ks * 8 + q + 4];
                    mma_tf32(s[0][nt], afr[0], bfr);
                    mma_tf32(s[1][nt], afr[1], bfr);
                }
            }

            // ---- bias + mask + online softmax (base-2 domain) ----
            const bool need_mask = (k0 + 63 > wrow_min);
#pragma unroll
            for (int mt = 0; mt < 2; mt++) {
                const int r0 = wrow_min + mt * 16 + g;
                const int r1 = r0 + 8;
                float mx0 = -1e30f, mx1 = -1e30f;
#pragma unroll
                for (int nt = 0; nt < 8; nt++) {
#pragma unroll
                    for (int jj = 0; jj < 2; jj++) {
                        int col = k0 + nt * 8 + q * 2 + jj;
                        float bias = slope2 * (float)col;
                        float v0 = fmaf(s[mt][nt][jj],     scale2, bias);
                        float v1 = fmaf(s[mt][nt][2 + jj], scale2, bias);
                        if (need_mask) {
                            if (col > r0) v0 = -1e30f;
                            if (col > r1) v1 = -1e30f;
                        }
                        s[mt][nt][jj]     = v0;
                        s[mt][nt][2 + jj] = v1;
                        mx0 = fmaxf(mx0, v0);
                        mx1 = fmaxf(mx1, v1);
                    }
                }
                mx0 = fmaxf(mx0, __shfl_xor_sync(0xffffffffu, mx0, 1));
                mx0 = fmaxf(mx0, __shfl_xor_sync(0xffffffffu, mx0, 2));
                mx1 = fmaxf(mx1, __shfl_xor_sync(0xffffffffu, mx1, 1));
                mx1 = fmaxf(mx1, __shfl_xor_sync(0xffffffffu, mx1, 2));

                float mn0 = fmaxf(mprev[mt][0], mx0);
                float mn1 = fmaxf(mprev[mt][1], mx1);
                float sum0 = 0.f, sum1 = 0.f;
#pragma unroll
                for (int nt = 0; nt < 8; nt++) {
#pragma unroll
                    for (int jj = 0; jj < 2; jj++) {
                        float p0 = exp2f(s[mt][nt][jj]     - mn0);
                        float p1 = exp2f(s[mt][nt][2 + jj] - mn1);
                        s[mt][nt][jj]     = p0;
                        s[mt][nt][2 + jj] = p1;
                        sum0 += p0;
                        sum1 += p1;
                    }
                }
                sum0 += __shfl_xor_sync(0xffffffffu, sum0, 1);
                sum0 += __shfl_xor_sync(0xffffffffu, sum0, 2);
                sum1 += __shfl_xor_sync(0xffffffffu, sum1, 1);
                sum1 += __shfl_xor_sync(0xffffffffu, sum1, 2);

                float al0 = exp2f(mprev[mt][0] - mn0);
                float al1 = exp2f(mprev[mt][1] - mn1);
                lrun[mt][0] = lrun[mt][0] * al0 + sum0;
                lrun[mt][1] = lrun[mt][1] * al1 + sum1;
                mprev[mt][0] = mn0;
                mprev[mt][1] = mn1;
#pragma unroll
                for (int nt = 0; nt < 8; nt++) {
                    o[mt][nt][0] *= al0;
                    o[mt][nt][1] *= al0;
                    o[mt][nt][2] *= al1;
                    o[mt][nt][3] *= al1;
                }

                // write P tile (per-warp private smem), tf32, STS.64 pairs
#pragma unroll
                for (int nt = 0; nt < 8; nt++) {
                    *(uint2*)&Pw[(mt * 16 + g)     * FSTR + nt * 8 + q * 2] =
                        make_uint2(f2tf32(s[mt][nt][0]), f2tf32(s[mt][nt][1]));
                    *(uint2*)&Pw[(mt * 16 + g + 8) * FSTR + nt * 8 + q * 2] =
                        make_uint2(f2tf32(s[mt][nt][2]), f2tf32(s[mt][nt][3]));
                }
            }
            __syncwarp();

            // ---- O += P @ V ----
#pragma unroll
            for (int ks = 0; ks < 8; ks++) {
                uint32_t afr[2][4];
#pragma unroll
                for (int mt = 0; mt < 2; mt++) {
                    afr[mt][0] = Pw[(mt * 16 + g)     * FSTR + ks * 8 + q];
                    afr[mt][1] = Pw[(mt * 16 + g + 8) * FSTR + ks * 8 + q];
                    afr[mt][2] = Pw[(mt * 16 + g)     * FSTR + ks * 8 + q + 4];
                    afr[mt][3] = Pw[(mt * 16 + g + 8) * FSTR + ks * 8 + q + 4];
                }
#pragma unroll
                for (int nt = 0; nt < 8; nt++) {
                    uint32_t bfr[2];
                    bfr[0] = Vs[(nt * 8 + g) * FSTR + ks * 8 + q];
                    bfr[1] = Vs[(nt * 8 + g) * FSTR + ks * 8 + q + 4];
                    mma_tf32(o[0][nt], afr[0], bfr);
                    mma_tf32(o[1][nt], afr[1], bfr);
                }
            }
        }

        // ---- epilogue: normalize, store [b, row, h*64 + d] ----
#pragma unroll
        for (int mt = 0; mt < 2; mt++) {
            float inv0 = 1.f / lrun[mt][0];
            float inv1 = 1.f / lrun[mt][1];
            int r0 = q0 + w * 32 + mt * 16 + g;
#pragma unroll
            for (int nt = 0; nt < 8; nt++) {
                int c = h * DH + nt * 8 + q * 2;
                *(float2*)&attn_out[(size_t)(b * SEQ + r0) * DIM + c] =
                    make_float2(o[mt][nt][0] * inv0, o[mt][nt][1] * inv0);
                *(float2*)&attn_out[(size_t)(b * SEQ + r0 + 8) * DIM + c] =
                    make_float2(o[mt][nt][2] * inv1, o[mt][nt][3] * inv1);
            }
        }
    }
}

// ---------------------------------------------------------------------------
extern "C" void kernel_launch(void* const* d_in, const int* in_sizes, int n_in,
                              void* d_out, int out_size) {
    const float* x      = (const float*)d_in[0];   // [2,2048,1024]
    const float* w_qkv  = (const float*)d_in[1];   // [1024,3072]
    const float* w_proj = (const float*)d_in[2];   // [1024,1024]
    float* out = (float*)d_out;                    // [2,2048,1024]

    float *qkv_ptr, *attn_ptr;
    cudaGetSymbolAddress((void**)&qkv_ptr, g_qkv);
    cudaGetSymbolAddress((void**)&attn_ptr, g_attn);

    cudaFuncSetAttribute(flash_mma, cudaFuncAttributeMaxDynamicSharedMemorySize,
                         (int)FLASH_SMEM);

    // 1) qkv = x @ w_qkv    [4096,1024]@[1024,3072]
    sgemm_tf32<<<dim3(3 * DIM / GBN, MTOT / GBM), 256>>>(x, w_qkv, qkv_ptr, MTOT, 3 * DIM, DIM);

    // 2) attention (balanced q-tile pairs)
    flash_mma<<<dim3(NQT / 2, BATCH * HEADS), 128, FLASH_SMEM>>>(qkv_ptr, attn_ptr);

    // 3) out = attn @ w_proj [4096,1024]@[1024,1024]
    sgemm_tf32<<<dim3(DIM / GBN, MTOT / GBM), 256>>>(attn_ptr, w_proj, out, MTOT, DIM, DIM);
}

// round 7
// speedup vs baseline: 1.0021x; 1.0004x over previous
#include <cuda_runtime.h>
#include <cuda_bf16.h>
#include <math.h>
#include <stdint.h>

// Problem constants
#define BATCH 2
#define SEQ   2048
#define DIM   1024
#define HEADS 16
#define DH    64
#define MTOT  (BATCH*SEQ)          // 4096 rows

// Scratch (allocation-free rule: __device__ globals)
__device__ float g_qkv[(size_t)MTOT * 3 * DIM];   // [4096, 3072]
__device__ float g_attn[(size_t)MTOT * DIM];      // [4096, 1024]

__device__ __forceinline__ uint32_t f2tf32(float v) {
    uint32_t o;
    asm("cvt.rna.tf32.f32 %0, %1;" : "=r"(o) : "f"(v));
    return o;
}

__device__ __forceinline__ void mma_tf32(float c[4], const uint32_t a[4], const uint32_t b[2]) {
    asm volatile(
        "mma.sync.aligned.m16n8k8.row.col.f32.tf32.tf32.f32 "
        "{%0,%1,%2,%3}, {%4,%5,%6,%7}, {%8,%9}, {%0,%1,%2,%3};"
        : "+f"(c[0]), "+f"(c[1]), "+f"(c[2]), "+f"(c[3])
        : "r"(a[0]), "r"(a[1]), "r"(a[2]), "r"(a[3]), "r"(b[0]), "r"(b[1]));
}

// ---------------------------------------------------------------------------
// TF32 tensor-core GEMM (unchanged from R1): C = A @ B, row-major fp32.
// ---------------------------------------------------------------------------
#define GBM 128
#define GBN 128
#define GBK 16
#define GSTRIDE 20

__global__ __launch_bounds__(256) void sgemm_tf32(const float* __restrict__ A,
                                                  const float* __restrict__ B,
                                                  float* __restrict__ C,
                                                  int M, int N, int K) {
    __shared__ uint32_t As[2][GBM][GSTRIDE];
    __shared__ uint32_t Bs[2][GBN][GSTRIDE];

    const int tid  = threadIdx.x;
    const int lane = tid & 31;
    const int wid  = tid >> 5;
    const int wm   = wid & 3;
    const int wn   = wid >> 2;
    const int g    = lane >> 2;
    const int q    = lane & 3;

    const int m0 = blockIdx.y * GBM;
    const int n0 = blockIdx.x * GBN;

    const int a_row  = tid >> 2;
    const int a_col4 = (tid & 3) * 4;
    const int b_k    = tid >> 4;
    const int b_n4   = (tid & 15) * 4;

    float acc[2][8][4];
#pragma unroll
    for (int i = 0; i < 2; i++)
#pragma unroll
        for (int j = 0; j < 8; j++)
#pragma unroll
            for (int r = 0; r < 4; r++) acc[i][j][r] = 0.f;

    const int ntiles = K / GBK;

    float4 ra[2], rb[2];
#pragma unroll
    for (int i = 0; i < 2; i++) {
        ra[i] = *(const float4*)&A[(size_t)(m0 + a_row + 64 * i) * K + a_col4];
        rb[i] = *(const float4*)&B[(size_t)b_k * N + n0 + b_n4 + 64 * i];
    }
#pragma unroll
    for (int i = 0; i < 2; i++) {
        int r = a_row + 64 * i;
        As[0][r][a_col4 + 0] = f2tf32(ra[i].x);
        As[0][r][a_col4 + 1] = f2tf32(ra[i].y);
        As[0][r][a_col4 + 2] = f2tf32(ra[i].z);
        As[0][r][a_col4 + 3] = f2tf32(ra[i].w);
        int n = b_n4 + 64 * i;
        Bs[0][n + 0][b_k] = f2tf32(rb[i].x);
        Bs[0][n + 1][b_k] = f2tf32(rb[i].y);
        Bs[0][n + 2][b_k] = f2tf32(rb[i].z);
        Bs[0][n + 3][b_k] = f2tf32(rb[i].w);
    }
    __syncthreads();

    for (int kt = 0; kt < ntiles; kt++) {
        const int cur = kt & 1, nxt = cur ^ 1;
        const bool more = (kt + 1 < ntiles);

        if (more) {
            int k0 = (kt + 1) * GBK;
#pragma unroll
            for (int i = 0; i < 2; i++) {
                ra[i] = *(const float4*)&A[(size_t)(m0 + a_row + 64 * i) * K + k0 + a_col4];
                rb[i] = *(const float4*)&B[(size_t)(k0 + b_k) * N + n0 + b_n4 + 64 * i];
            }
        }

#pragma unroll
        for (int ks = 0; ks < 2; ks++) {
            uint32_t afr[2][4];
#pragma unroll
            for (int mt = 0; mt < 2; mt++) {
                int rb0 = wm * 32 + mt * 16;
                afr[mt][0] = As[cur][rb0 + g][ks * 8 + q];
                afr[mt][1] = As[cur][rb0 + g + 8][ks * 8 + q];
                afr[mt][2] = As[cur][rb0 + g][ks * 8 + q + 4];
                afr[mt][3] = As[cur][rb0 + g + 8][ks * 8 + q + 4];
            }
#pragma unroll
            for (int nt = 0; nt < 8; nt++) {
                int nb = wn * 64 + nt * 8;
                uint32_t bfr[2];
                bfr[0] = Bs[cur][nb + g][ks * 8 + q];
                bfr[1] = Bs[cur][nb + g][ks * 8 + q + 4];
                mma_tf32(acc[0][nt], afr[0], bfr);
                mma_tf32(acc[1][nt], afr[1], bfr);
            }
        }

        if (more) {
#pragma unroll
            for (int i = 0; i < 2; i++) {
                int r = a_row + 64 * i;
                As[nxt][r][a_col4 + 0] = f2tf32(ra[i].x);
                As[nxt][r][a_col4 + 1] = f2tf32(ra[i].y);
                As[nxt][r][a_col4 + 2] = f2tf32(ra[i].z);
                As[nxt][r][a_col4 + 3] = f2tf32(ra[i].w);
                int n = b_n4 + 64 * i;
                Bs[nxt][n + 0][b_k] = f2tf32(rb[i].x);
                Bs[nxt][n + 1][b_k] = f2tf32(rb[i].y);
                Bs[nxt][n + 2][b_k] = f2tf32(rb[i].z);
                Bs[nxt][n + 3][b_k] = f2tf32(rb[i].w);
            }
        }
        __syncthreads();
    }

#pragma unroll
    for (int mt = 0; mt < 2; mt++) {
        int r0 = m0 + wm * 32 + mt * 16 + g;
#pragma unroll
        for (int nt = 0; nt < 8; nt++) {
            int c0 = n0 + wn * 64 + nt * 8 + q * 2;
            *(float2*)&C[(size_t)r0 * N + c0]       = make_float2(acc[mt][nt][0], acc[mt][nt][1]);
            *(float2*)&C[(size_t)(r0 + 8) * N + c0] = make_float2(acc[mt][nt][2], acc[mt][nt][3]);
        }
    }
}

// ---------------------------------------------------------------------------
// Flash attention with TF32 mma.sync tensor cores.
// Block: 128 threads (4 warps) handles the q-tile PAIR {qi, 15-qi} for one
// (b,h) -> perfectly balanced causal work (34 key-tiles per block).
// Each warp: 32 q-rows x 64 keys. Softmax in mma C-fragment layout, base-2.
// Smem: Qs[128][68] tf32, Ks[64][68] (key-major), Vs[64][68] (d-major,
// i.e. V transposed), Ps[4][32][68] per-warp P tiles.
// ---------------------------------------------------------------------------
#define FSTR 68
#define NQT  (SEQ/128)   // 16 q-tiles
#define FLASH_SMEM ((128*FSTR + 64*FSTR + 64*FSTR + 4*32*FSTR) * 4)

__global__ __launch_bounds__(128) void flash_mma(const float* __restrict__ qkv,
                                                 float* __restrict__ attn_out) {
    extern __shared__ uint32_t sm[];
    uint32_t* Qs = sm;                       // [qrow][d]
    uint32_t* Ks = Qs + 128 * FSTR;          // [key][d]
    uint32_t* Vs = Ks + 64 * FSTR;           // [d][key]  (V^T)
    uint32_t* Ps = Vs + 64 * FSTR;           // [warp][row][key]

    const int tid  = threadIdx.x;
    const int lane = tid & 31;
    const int w    = tid >> 5;
    const int g    = lane >> 2;
    const int q    = lane & 3;

    const int bh = blockIdx.y;
    const int b  = bh >> 4;
    const int h  = bh & 15;

    const float LOG2E  = 1.44269504088896f;
    const float scale2 = 0.125f * LOG2E;                       // Dh^-0.5 * log2(e)
    const float slope2 = exp2f(-0.5f * (float)(h + 1)) * LOG2E;

    const float* qb = qkv + (size_t)b * SEQ * (3 * DIM) + h * DH;
    const float* kb = qb + DIM;
    const float* vb = qb + 2 * DIM;

    uint32_t* Pw = Ps + w * 32 * FSTR;

#pragma unroll 1
    for (int half = 0; half < 2; half++) {
        const int qi = half ? (NQT - 1 - blockIdx.x) : blockIdx.x;
        const int q0 = qi * 128;

        __syncthreads();   // Qs/Ks/Vs reuse across halves

        // ---- load Q tile (rows q0..q0+127) as tf32, [row][d] ----
        {
            int r  = tid >> 4;
            int d4 = (tid & 15) * 4;
#pragma unroll
            for (int it = 0; it < 16; it++, r += 8) {
                float4 v = *(const float4*)&qb[(size_t)(q0 + r) * (3 * DIM) + d4];
                *(uint4*)&Qs[r * FSTR + d4] =
                    make_uint4(f2tf32(v.x), f2tf32(v.y), f2tf32(v.z), f2tf32(v.w));
            }
        }

        // per-row state (rows: mt*16+g and mt*16+g+8 within warp tile)
        float o[2][8][4];
        float mprev[2][2], lrun[2][2];
#pragma unroll
        for (int mt = 0; mt < 2; mt++) {
            mprev[mt][0] = mprev[mt][1] = -1e30f;
            lrun[mt][0]  = lrun[mt][1]  = 0.f;
#pragma unroll
            for (int nt = 0; nt < 8; nt++)
#pragma unroll
                for (int r = 0; r < 4; r++) o[mt][nt][r] = 0.f;
        }

        const int nkt = 2 * qi + 2;
        const int wrow_min = q0 + w * 32;       // warp's first q-row
        const int wrow_max = wrow_min + 31;

        for (int kt = 0; kt < nkt; kt++) {
            const int k0 = kt * 64;
            __syncthreads();   // previous tile's PV reads done

            // ---- load K [key][d] and V^T [d][key] ----
            {
                int key = tid >> 4;
                int d4  = (tid & 15) * 4;
#pragma unroll
                for (int it = 0; it < 8; it++, key += 8) {
                    float4 kv = *(const float4*)&kb[(size_t)(k0 + key) * (3 * DIM) + d4];
                    *(uint4*)&Ks[key * FSTR + d4] =
                        make_uint4(f2tf32(kv.x), f2tf32(kv.y), f2tf32(kv.z), f2tf32(kv.w));
                    float4 vv = *(const float4*)&vb[(size_t)(k0 + key) * (3 * DIM) + d4];
                    Vs[(d4 + 0) * FSTR + key] = f2tf32(vv.x);
                    Vs[(d4 + 1) * FSTR + key] = f2tf32(vv.y);
                    Vs[(d4 + 2) * FSTR + key] = f2tf32(vv.z);
                    Vs[(d4 + 3) * FSTR + key] = f2tf32(vv.w);
                }
            }
            __syncthreads();

            // warp-uniform skip: entire tile above the diagonal for this warp
            if (k0 > wrow_max) continue;

            // ---- S = Q @ K^T ----
            float s[2][8][4];
#pragma unroll
            for (int mt = 0; mt < 2; mt++)
#pragma unroll
                for (int nt = 0; nt < 8; nt++)
#pragma unroll
                    for (int r = 0; r < 4; r++) s[mt][nt][r] = 0.f;

#pragma unroll
            for (int ks = 0; ks < 8; ks++) {
                uint32_t afr[2][4];
#pragma unroll
                for (int mt = 0; mt < 2; mt++) {
                    int rb0 = w * 32 + mt * 16;
                    afr[mt][0] = Qs[(rb0 + g)     * FSTR + ks * 8 + q];
                    afr[mt][1] = Qs[(rb0 + g + 8) * FSTR + ks * 8 + q];
                    afr[mt][2] = Qs[(rb0 + g)     * FSTR + ks * 8 + q + 4];
                    afr[mt][3] = Qs[(rb0 + g + 8) * FSTR + ks * 8 + q + 4];
                }
#pragma unroll
                for (int nt = 0; nt < 8; nt++) {
                    uint32_t bfr[2];
                    bfr[0] = Ks[(nt * 8 + g) * FSTR + ks * 8 + q];
                    bfr[1] = Ks[(nt * 8 + g) * FSTR + ks * 8 + q + 4];
                    mma_tf32(s[0][nt], afr[0], bfr);
                    mma_tf32(s[1][nt], afr[1], bfr);
                }
            }

            // ---- bias + mask + online softmax (base-2 domain) ----
            const bool need_mask = (k0 + 63 > wrow_min);
#pragma unroll
            for (int mt = 0; mt < 2; mt++) {
                const int r0 = wrow_min + mt * 16 + g;
                const int r1 = r0 + 8;
                float mx0 = -1e30f, mx1 = -1e30f;
#pragma unroll
                for (int nt = 0; nt < 8; nt++) {
#pragma unroll
                    for (int jj = 0; jj < 2; jj++) {
                        int col = k0 + nt * 8 + q * 2 + jj;
                        float bias = slope2 * (float)col;
                        float v0 = fmaf(s[mt][nt][jj],     scale2, bias);
                        float v1 = fmaf(s[mt][nt][2 + jj], scale2, bias);
                        if (need_mask) {
                            if (col > r0) v0 = -1e30f;
                            if (col > r1) v1 = -1e30f;
                        }
                        s[mt][nt][jj]     = v0;
                        s[mt][nt][2 + jj] = v1;
                        mx0 = fmaxf(mx0, v0);
                        mx1 = fmaxf(mx1, v1);
                    }
                }
                mx0 = fmaxf(mx0, __shfl_xor_sync(0xffffffffu, mx0, 1));
                mx0 = fmaxf(mx0, __shfl_xor_sync(0xffffffffu, mx0, 2));
                mx1 = fmaxf(mx1, __shfl_xor_sync(0xffffffffu, mx1, 1));
                mx1 = fmaxf(mx1, __shfl_xor_sync(0xffffffffu, mx1, 2));

                float mn0 = fmaxf(mprev[mt][0], mx0);
                float mn1 = fmaxf(mprev[mt][1], mx1);
                float sum0 = 0.f, sum1 = 0.f;
#pragma unroll
                for (int nt = 0; nt < 8; nt++) {
#pragma unroll
                    for (int jj = 0; jj < 2; jj++) {
                        float p0 = exp2f(s[mt][nt][jj]     - mn0);
                        float p1 = exp2f(s[mt][nt][2 + jj] - mn1);
                        s[mt][nt][jj]     = p0;
                        s[mt][nt][2 + jj] = p1;
                        sum0 += p0;
                        sum1 += p1;
                    }
                }
                sum0 += __shfl_xor_sync(0xffffffffu, sum0, 1);
                sum0 += __shfl_xor_sync(0xffffffffu, sum0, 2);
                sum1 += __shfl_xor_sync(0xffffffffu, sum1, 1);
                sum1 += __shfl_xor_sync(0xffffffffu, sum1, 2);

                float al0 = exp2f(mprev[mt][0] - mn0);
                float al1 = exp2f(mprev[mt][1] - mn1);
                lrun[mt][0] = lrun[mt][0] * al0 + sum0;
                lrun[mt][1] = lrun[mt][1] * al1 + sum1;
                mprev[mt][0] = mn0;
                mprev[mt][1] = mn1;
#pragma unroll
                for (int nt = 0; nt < 8; nt++) {
                    o[mt][nt][0] *= al0;
                    o[mt][nt][1] *= al0;
                    o[mt][nt][2] *= al1;
                    o[mt][nt][3] *= al1;
                }

                // write P tile (per-warp private smem), tf32, STS.64 pairs
#pragma unroll
                for (int nt = 0; nt < 8; nt++) {
                    *(uint2*)&Pw[(mt * 16 + g)     * FSTR + nt * 8 + q * 2] =
                        make_uint2(f2tf32(s[mt][nt][0]), f2tf32(s[mt][nt][1]));
                    *(uint2*)&Pw[(mt * 16 + g + 8) * FSTR + nt * 8 + q * 2] =
                        make_uint2(f2tf32(s[mt][nt][2]), f2tf32(s[mt][nt][3]));
                }
            }
            __syncwarp();

            // ---- O += P @ V ----
#pragma unroll
            for (int ks = 0; ks < 8; ks++) {
                uint32_t afr[2][4];
#pragma unroll
                for (int mt = 0; mt < 2; mt++) {
                    afr[mt][0] = Pw[(mt * 16 + g)     * FSTR + ks * 8 + q];
                    afr[mt][1] = Pw[(mt * 16 + g + 8) * FSTR + ks * 8 + q];
                    afr[mt][2] = Pw[(mt * 16 + g)     * FSTR + ks * 8 + q + 4];
                    afr[mt][3] = Pw[(mt * 16 + g + 8) * FSTR + ks * 8 + q + 4];
                }
#pragma unroll
                for (int nt = 0; nt < 8; nt++) {
                    uint32_t bfr[2];
                    bfr[0] = Vs[(nt * 8 + g) * FSTR + ks * 8 + q];
                    bfr[1] = Vs[(nt * 8 + g) * FSTR + ks * 8 + q + 4];
                    mma_tf32(o[0][nt], afr[0], bfr);
                    mma_tf32(o[1][nt], afr[1], bfr);
                }
            }
        }

        // ---- epilogue: normalize, store [b, row, h*64 + d] ----
#pragma unroll
        for (int mt = 0; mt < 2; mt++) {
            float inv0 = 1.f / lrun[mt][0];
            float inv1 = 1.f / lrun[mt][1];
            int r0 = q0 + w * 32 + mt * 16 + g;
#pragma unroll
            for (int nt = 0; nt < 8; nt++) {
                int c = h * DH + nt * 8 + q * 2;
                *(float2*)&attn_out[(size_t)(b * SEQ + r0) * DIM + c] =
                    make_float2(o[mt][nt][0] * inv0, o[mt][nt][1] * inv0);
                *(float2*)&attn_out[(size_t)(b * SEQ + r0 + 8) * DIM + c] =
                    make_float2(o[mt][nt][2] * inv1, o[mt][nt][3] * inv1);
            }
        }
    }
}

// ---------------------------------------------------------------------------
extern "C" void kernel_launch(void* const* d_in, const int* in_sizes, int n_in,
                              void* d_out, int out_size) {
    const float* x      = (const float*)d_in[0];   // [2,2048,1024]
    const float* w_qkv  = (const float*)d_in[1];   // [1024,3072]
    const float* w_proj = (const float*)d_in[2];   // [1024,1024]
    float* out = (float*)d_out;                    // [2,2048,1024]

    float *qkv_ptr, *attn_ptr;
    cudaGetSymbolAddress((void**)&qkv_ptr, g_qkv);
    cudaGetSymbolAddress((void**)&attn_ptr, g_attn);

    cudaFuncSetAttribute(flash_mma, cudaFuncAttributeMaxDynamicSharedMemorySize,
                         (int)FLASH_SMEM);

    // 1) qkv = x @ w_qkv    [4096,1024]@[1024,3072]
    sgemm_tf32<<<dim3(3 * DIM / GBN, MTOT / GBM), 256>>>(x, w_qkv, qkv_ptr, MTOT, 3 * DIM, DIM);

    // 2) attention (balanced q-tile pairs)
    flash_mma<<<dim3(NQT / 2, BATCH * HEADS), 128, FLASH_SMEM>>>(qkv_ptr, attn_ptr);

    // 3) out = attn @ w_proj [4096,1024]@[1024,1024]
    sgemm_tf32<<<dim3(DIM / GBN, MTOT / GBM), 256>>>(attn_ptr, w_proj, out, MTOT, DIM, DIM);
}

// round 8
// speedup vs baseline: 1.2285x; 1.2259x over previous
#include <cuda_runtime.h>
#include <cuda_bf16.h>
#include <math.h>
#include <stdint.h>

// Problem constants
#define BATCH 2
#define SEQ   2048
#define DIM   1024
#define HEADS 16
#define DH    64
#define MTOT  (BATCH*SEQ)          // 4096 rows

// Scratch (allocation-free rule: __device__ globals)
__device__ float g_qkv[(size_t)MTOT * 3 * DIM];   // [4096, 3072]
__device__ float g_attn[(size_t)MTOT * DIM];      // [4096, 1024]

__device__ __forceinline__ uint32_t f2tf32(float v) {
    uint32_t o;
    asm("cvt.rna.tf32.f32 %0, %1;" : "=r"(o) : "f"(v));
    return o;
}

__device__ __forceinline__ void mma_tf32(float c[4], const uint32_t a[4], const uint32_t b[2]) {
    asm volatile(
        "mma.sync.aligned.m16n8k8.row.col.f32.tf32.tf32.f32 "
        "{%0,%1,%2,%3}, {%4,%5,%6,%7}, {%8,%9}, {%0,%1,%2,%3};"
        : "+f"(c[0]), "+f"(c[1]), "+f"(c[2]), "+f"(c[3])
        : "r"(a[0]), "r"(a[1]), "r"(a[2]), "r"(a[3]), "r"(b[0]), "r"(b[1]));
}

// ---------------------------------------------------------------------------
// TF32 tensor-core GEMM: C = A @ B, row-major fp32.
// B tile now stored NATURAL [k][n] with pad 136 (8 mod 32):
//   - STS.128 stores conflict-free
//   - fragment loads Bs[k][n] conflict-free (banks 8q+8nt+g all distinct)
// ---------------------------------------------------------------------------
#define GBM 128
#define GBN 128
#define GBK 16
#define GSTRIDE 20
#define BSTRIDE 136

__global__ __launch_bounds__(256) void sgemm_tf32(const float* __restrict__ A,
                                                  const float* __restrict__ B,
                                                  float* __restrict__ C,
                                                  int M, int N, int K) {
    __shared__ uint32_t As[2][GBM][GSTRIDE];   // [m][k], pad 20 (STS scalar conflict-free)
    __shared__ uint32_t Bs[2][GBK][BSTRIDE];   // [k][n], pad 136

    const int tid  = threadIdx.x;
    const int lane = tid & 31;
    const int wid  = tid >> 5;
    const int wm   = wid & 3;
    const int wn   = wid >> 2;
    const int g    = lane >> 2;
    const int q    = lane & 3;

    const int m0 = blockIdx.y * GBM;
    const int n0 = blockIdx.x * GBN;

    const int a_row  = tid >> 2;
    const int a_col4 = (tid & 3) * 4;
    const int b_k    = tid >> 4;          // 0..15
    const int b_n4   = (tid & 15) * 4;    // 0..60 (+64)

    float acc[2][8][4];
#pragma unroll
    for (int i = 0; i < 2; i++)
#pragma unroll
        for (int j = 0; j < 8; j++)
#pragma unroll
            for (int r = 0; r < 4; r++) acc[i][j][r] = 0.f;

    const int ntiles = K / GBK;

    float4 ra[2], rb[2];
#pragma unroll
    for (int i = 0; i < 2; i++) {
        ra[i] = *(const float4*)&A[(size_t)(m0 + a_row + 64 * i) * K + a_col4];
        rb[i] = *(const float4*)&B[(size_t)b_k * N + n0 + b_n4 + 64 * i];
    }
#pragma unroll
    for (int i = 0; i < 2; i++) {
        int r = a_row + 64 * i;
        As[0][r][a_col4 + 0] = f2tf32(ra[i].x);
        As[0][r][a_col4 + 1] = f2tf32(ra[i].y);
        As[0][r][a_col4 + 2] = f2tf32(ra[i].z);
        As[0][r][a_col4 + 3] = f2tf32(ra[i].w);
        *(uint4*)&Bs[0][b_k][b_n4 + 64 * i] =
            make_uint4(f2tf32(rb[i].x), f2tf32(rb[i].y), f2tf32(rb[i].z), f2tf32(rb[i].w));
    }
    __syncthreads();

    for (int kt = 0; kt < ntiles; kt++) {
        const int cur = kt & 1, nxt = cur ^ 1;
        const bool more = (kt + 1 < ntiles);

        if (more) {
            int k0 = (kt + 1) * GBK;
#pragma unroll
            for (int i = 0; i < 2; i++) {
                ra[i] = *(const float4*)&A[(size_t)(m0 + a_row + 64 * i) * K + k0 + a_col4];
                rb[i] = *(const float4*)&B[(size_t)(k0 + b_k) * N + n0 + b_n4 + 64 * i];
            }
        }

#pragma unroll
        for (int ks = 0; ks < 2; ks++) {
            uint32_t afr[2][4];
#pragma unroll
            for (int mt = 0; mt < 2; mt++) {
                int rb0 = wm * 32 + mt * 16;
                afr[mt][0] = As[cur][rb0 + g][ks * 8 + q];
                afr[mt][1] = As[cur][rb0 + g + 8][ks * 8 + q];
                afr[mt][2] = As[cur][rb0 + g][ks * 8 + q + 4];
                afr[mt][3] = As[cur][rb0 + g + 8][ks * 8 + q + 4];
            }
#pragma unroll
            for (int nt = 0; nt < 8; nt++) {
                int nb = wn * 64 + nt * 8;
                uint32_t bfr[2];
                bfr[0] = Bs[cur][ks * 8 + q][nb + g];
                bfr[1] = Bs[cur][ks * 8 + q + 4][nb + g];
                mma_tf32(acc[0][nt], afr[0], bfr);
                mma_tf32(acc[1][nt], afr[1], bfr);
            }
        }

        if (more) {
#pragma unroll
            for (int i = 0; i < 2; i++) {
                int r = a_row + 64 * i;
                As[nxt][r][a_col4 + 0] = f2tf32(ra[i].x);
                As[nxt][r][a_col4 + 1] = f2tf32(ra[i].y);
                As[nxt][r][a_col4 + 2] = f2tf32(ra[i].z);
                As[nxt][r][a_col4 + 3] = f2tf32(ra[i].w);
                *(uint4*)&Bs[nxt][b_k][b_n4 + 64 * i] =
                    make_uint4(f2tf32(rb[i].x), f2tf32(rb[i].y), f2tf32(rb[i].z), f2tf32(rb[i].w));
            }
        }
        __syncthreads();
    }

#pragma unroll
    for (int mt = 0; mt < 2; mt++) {
        int r0 = m0 + wm * 32 + mt * 16 + g;
#pragma unroll
        for (int nt = 0; nt < 8; nt++) {
            int c0 = n0 + wn * 64 + nt * 8 + q * 2;
            *(float2*)&C[(size_t)r0 * N + c0]       = make_float2(acc[mt][nt][0], acc[mt][nt][1]);
            *(float2*)&C[(size_t)(r0 + 8) * N + c0] = make_float2(acc[mt][nt][2], acc[mt][nt][3]);
        }
    }
}

// ---------------------------------------------------------------------------
// Flash attention with TF32 mma.sync tensor cores.
// V tile now stored NATURAL [key][dh] with pad 72 (8 mod 32):
//   STS.128 conflict-free; PV fragment loads Vs[k][n] conflict-free.
// ---------------------------------------------------------------------------
#define FSTR 68
#define VSTR 72
#define NQT  (SEQ/128)   // 16 q-tiles
#define FLASH_SMEM ((128*FSTR + 64*FSTR + 64*VSTR + 4*32*FSTR) * 4)

__global__ __launch_bounds__(128) void flash_mma(const float* __restrict__ qkv,
                                                 float* __restrict__ attn_out) {
    extern __shared__ uint32_t sm[];
    uint32_t* Qs = sm;                       // [qrow][d]   pad 68
    uint32_t* Ks = Qs + 128 * FSTR;          // [key][d]    pad 68
    uint32_t* Vs = Ks + 64 * FSTR;           // [key][dh]   pad 72 (natural)
    uint32_t* Ps = Vs + 64 * VSTR;           // [warp][row][key] pad 68

    const int tid  = threadIdx.x;
    const int lane = tid & 31;
    const int w    = tid >> 5;
    const int g    = lane >> 2;
    const int q    = lane & 3;

    const int bh = blockIdx.y;
    const int b  = bh >> 4;
    const int h  = bh & 15;

    const float LOG2E  = 1.44269504088896f;
    const float scale2 = 0.125f * LOG2E;
    const float slope2 = exp2f(-0.5f * (float)(h + 1)) * LOG2E;

    const float* qb = qkv + (size_t)b * SEQ * (3 * DIM) + h * DH;
    const float* kb = qb + DIM;
    const float* vb = qb + 2 * DIM;

    uint32_t* Pw = Ps + w * 32 * FSTR;

#pragma unroll 1
    for (int half = 0; half < 2; half++) {
        const int qi = half ? (NQT - 1 - blockIdx.x) : blockIdx.x;
        const int q0 = qi * 128;

        __syncthreads();

        // ---- load Q tile as tf32, [row][d] ----
        {
            int r  = tid >> 4;
            int d4 = (tid & 15) * 4;
#pragma unroll
            for (int it = 0; it < 16; it++, r += 8) {
                float4 v = *(const float4*)&qb[(size_t)(q0 + r) * (3 * DIM) + d4];
                *(uint4*)&Qs[r * FSTR + d4] =
                    make_uint4(f2tf32(v.x), f2tf32(v.y), f2tf32(v.z), f2tf32(v.w));
            }
        }

        float o[2][8][4];
        float mprev[2][2], lrun[2][2];
#pragma unroll
        for (int mt = 0; mt < 2; mt++) {
            mprev[mt][0] = mprev[mt][1] = -1e30f;
            lrun[mt][0]  = lrun[mt][1]  = 0.f;
#pragma unroll
            for (int nt = 0; nt < 8; nt++)
#pragma unroll
                for (int r = 0; r < 4; r++) o[mt][nt][r] = 0.f;
        }

        const int nkt = 2 * qi + 2;
        const int wrow_min = q0 + w * 32;
        const int wrow_max = wrow_min + 31;

        for (int kt = 0; kt < nkt; kt++) {
            const int k0 = kt * 64;
            __syncthreads();

            // ---- load K [key][d] tf32 and V [key][dh] tf32 (both natural) ----
            {
                int key = tid >> 4;
                int d4  = (tid & 15) * 4;
#pragma unroll
                for (int it = 0; it < 8; it++, key += 8) {
                    float4 kv = *(const float4*)&kb[(size_t)(k0 + key) * (3 * DIM) + d4];
                    *(uint4*)&Ks[key * FSTR + d4] =
                        make_uint4(f2tf32(kv.x), f2tf32(kv.y), f2tf32(kv.z), f2tf32(kv.w));
                    float4 vv = *(const float4*)&vb[(size_t)(k0 + key) * (3 * DIM) + d4];
                    *(uint4*)&Vs[key * VSTR + d4] =
                        make_uint4(f2tf32(vv.x), f2tf32(vv.y), f2tf32(vv.z), f2tf32(vv.w));
                }
            }
            __syncthreads();

            if (k0 > wrow_max) continue;

            // ---- S = Q @ K^T ----
            float s[2][8][4];
#pragma unroll
            for (int mt = 0; mt < 2; mt++)
#pragma unroll
                for (int nt = 0; nt < 8; nt++)
#pragma unroll
                    for (int r = 0; r < 4; r++) s[mt][nt][r] = 0.f;

#pragma unroll
            for (int ks = 0; ks < 8; ks++) {
                uint32_t afr[2][4];
#pragma unroll
                for (int mt = 0; mt < 2; mt++) {
                    int rb0 = w * 32 + mt * 16;
                    afr[mt][0] = Qs[(rb0 + g)     * FSTR + ks * 8 + q];
                    afr[mt][1] = Qs[(rb0 + g + 8) * FSTR + ks * 8 + q];
                    afr[mt][2] = Qs[(rb0 + g)     * FSTR + ks * 8 + q + 4];
                    afr[mt][3] = Qs[(rb0 + g + 8) * FSTR + ks * 8 + q + 4];
                }
#pragma unroll
                for (int nt = 0; nt < 8; nt++) {
                    uint32_t bfr[2];
                    bfr[0] = Ks[(nt * 8 + g) * FSTR + ks * 8 + q];
                    bfr[1] = Ks[(nt * 8 + g) * FSTR + ks * 8 + q + 4];
                    mma_tf32(s[0][nt], afr[0], bfr);
                    mma_tf32(s[1][nt], afr[1], bfr);
                }
            }

            // ---- bias + mask + online softmax (base-2) ----
            const bool need_mask = (k0 + 63 > wrow_min);
#pragma unroll
            for (int mt = 0; mt < 2; mt++) {
                const int r0 = wrow_min + mt * 16 + g;
                const int r1 = r0 + 8;
                float mx0 = -1e30f, mx1 = -1e30f;
#pragma unroll
                for (int nt = 0; nt < 8; nt++) {
#pragma unroll
                    for (int jj = 0; jj < 2; jj++) {
                        int col = k0 + nt * 8 + q * 2 + jj;
                        float bias = slope2 * (float)col;
                        float v0 = fmaf(s[mt][nt][jj],     scale2, bias);
                        float v1 = fmaf(s[mt][nt][2 + jj], scale2, bias);
                        if (need_mask) {
                            if (col > r0) v0 = -1e30f;
                            if (col > r1) v1 = -1e30f;
                        }
                        s[mt][nt][jj]     = v0;
                        s[mt][nt][2 + jj] = v1;
                        mx0 = fmaxf(mx0, v0);
                        mx1 = fmaxf(mx1, v1);
                    }
                }
                mx0 = fmaxf(mx0, __shfl_xor_sync(0xffffffffu, mx0, 1));
                mx0 = fmaxf(mx0, __shfl_xor_sync(0xffffffffu, mx0, 2));
                mx1 = fmaxf(mx1, __shfl_xor_sync(0xffffffffu, mx1, 1));
                mx1 = fmaxf(mx1, __shfl_xor_sync(0xffffffffu, mx1, 2));

                float mn0 = fmaxf(mprev[mt][0], mx0);
                float mn1 = fmaxf(mprev[mt][1], mx1);
                float sum0 = 0.f, sum1 = 0.f;
#pragma unroll
                for (int nt = 0; nt < 8; nt++) {
#pragma unroll
                    for (int jj = 0; jj < 2; jj++) {
                        float p0 = exp2f(s[mt][nt][jj]     - mn0);
                        float p1 = exp2f(s[mt][nt][2 + jj] - mn1);
                        s[mt][nt][jj]     = p0;
                        s[mt][nt][2 + jj] = p1;
                        sum0 += p0;
                        sum1 += p1;
                    }
                }
                sum0 += __shfl_xor_sync(0xffffffffu, sum0, 1);
                sum0 += __shfl_xor_sync(0xffffffffu, sum0, 2);
                sum1 += __shfl_xor_sync(0xffffffffu, sum1, 1);
                sum1 += __shfl_xor_sync(0xffffffffu, sum1, 2);

                float al0 = exp2f(mprev[mt][0] - mn0);
                float al1 = exp2f(mprev[mt][1] - mn1);
                lrun[mt][0] = lrun[mt][0] * al0 + sum0;
                lrun[mt][1] = lrun[mt][1] * al1 + sum1;
                mprev[mt][0] = mn0;
                mprev[mt][1] = mn1;
#pragma unroll
                for (int nt = 0; nt < 8; nt++) {
                    o[mt][nt][0] *= al0;
                    o[mt][nt][1] *= al0;
                    o[mt][nt][2] *= al1;
                    o[mt][nt][3] *= al1;
                }

#pragma unroll
                for (int nt = 0; nt < 8; nt++) {
                    *(uint2*)&Pw[(mt * 16 + g)     * FSTR + nt * 8 + q * 2] =
                        make_uint2(f2tf32(s[mt][nt][0]), f2tf32(s[mt][nt][1]));
                    *(uint2*)&Pw[(mt * 16 + g + 8) * FSTR + nt * 8 + q * 2] =
                        make_uint2(f2tf32(s[mt][nt][2]), f2tf32(s[mt][nt][3]));
                }
            }
            __syncwarp();

            // ---- O += P @ V  (V natural [key][dh], fragments from [k][n]) ----
#pragma unroll
            for (int ks = 0; ks < 8; ks++) {
                uint32_t afr[2][4];
#pragma unroll
                for (int mt = 0; mt < 2; mt++) {
                    afr[mt][0] = Pw[(mt * 16 + g)     * FSTR + ks * 8 + q];
                    afr[mt][1] = Pw[(mt * 16 + g + 8) * FSTR + ks * 8 + q];
                    afr[mt][2] = Pw[(mt * 16 + g)     * FSTR + ks * 8 + q + 4];
                    afr[mt][3] = Pw[(mt * 16 + g + 8) * FSTR + ks * 8 + q + 4];
                }
#pragma unroll
                for (int nt = 0; nt < 8; nt++) {
                    uint32_t bfr[2];
                    bfr[0] = Vs[(ks * 8 + q)     * VSTR + nt * 8 + g];
                    bfr[1] = Vs[(ks * 8 + q + 4) * VSTR + nt * 8 + g];
                    mma_tf32(o[0][nt], afr[0], bfr);
                    mma_tf32(o[1][nt], afr[1], bfr);
                }
            }
        }

        // ---- epilogue ----
#pragma unroll
        for (int mt = 0; mt < 2; mt++) {
            float inv0 = 1.f / lrun[mt][0];
            float inv1 = 1.f / lrun[mt][1];
            int r0 = q0 + w * 32 + mt * 16 + g;
#pragma unroll
            for (int nt = 0; nt < 8; nt++) {
                int c = h * DH + nt * 8 + q * 2;
                *(float2*)&attn_out[(size_t)(b * SEQ + r0) * DIM + c] =
                    make_float2(o[mt][nt][0] * inv0, o[mt][nt][1] * inv0);
                *(float2*)&attn_out[(size_t)(b * SEQ + r0 + 8) * DIM + c] =
                    make_float2(o[mt][nt][2] * inv1, o[mt][nt][3] * inv1);
            }
        }
    }
}

// ---------------------------------------------------------------------------
extern "C" void kernel_launch(void* const* d_in, const int* in_sizes, int n_in,
                              void* d_out, int out_size) {
    const float* x      = (const float*)d_in[0];   // [2,2048,1024]
    const float* w_qkv  = (const float*)d_in[1];   // [1024,3072]
    const float* w_proj = (const float*)d_in[2];   // [1024,1024]
    float* out = (float*)d_out;                    // [2,2048,1024]

    float *qkv_ptr, *attn_ptr;
    cudaGetSymbolAddress((void**)&qkv_ptr, g_qkv);
    cudaGetSymbolAddress((void**)&attn_ptr, g_attn);

    cudaFuncSetAttribute(flash_mma, cudaFuncAttributeMaxDynamicSharedMemorySize,
                         (int)FLASH_SMEM);

    // 1) qkv = x @ w_qkv    [4096,1024]@[1024,3072]
    sgemm_tf32<<<dim3(3 * DIM / GBN, MTOT / GBM), 256>>>(x, w_qkv, qkv_ptr, MTOT, 3 * DIM, DIM);

    // 2) attention (balanced q-tile pairs)
    flash_mma<<<dim3(NQT / 2, BATCH * HEADS), 128, FLASH_SMEM>>>(qkv_ptr, attn_ptr);

    // 3) out = attn @ w_proj [4096,1024]@[1024,1024]
    sgemm_tf32<<<dim3(DIM / GBN, MTOT / GBM), 256>>>(attn_ptr, w_proj, out, MTOT, DIM, DIM);
}

// round 10
// speedup vs baseline: 1.4945x; 1.2165x over previous
#include <cuda_runtime.h>
#include <cuda_fp16.h>
#include <math.h>
#include <stdint.h>

// Problem constants
#define BATCH 2
#define SEQ   2048
#define DIM   1024
#define HEADS 16
#define DH    64
#define MTOT  (BATCH*SEQ)          // 4096 rows

// Scratch (allocation-free rule: __device__ globals)
__device__ __half g_xh[(size_t)MTOT * DIM];          // x as half
__device__ __half g_wqkv_h[(size_t)DIM * 3 * DIM];   // w_qkv as half [1024][3072]
__device__ __half g_wproj_h[(size_t)DIM * DIM];      // w_proj as half
__device__ __half g_qkv[(size_t)MTOT * 3 * DIM];     // qkv as half
__device__ __half g_attn[(size_t)MTOT * DIM];        // attn out as half

// ---------------------------------------------------------------------------
// PTX helpers
// ---------------------------------------------------------------------------
__device__ __forceinline__ uint32_t smem_u32(const void* p) {
    uint32_t a;
    asm("{ .reg .u64 t; cvta.to.shared.u64 t, %1; cvt.u32.u64 %0, t; }" : "=r"(a) : "l"(p));
    return a;
}

__device__ __forceinline__ void ldsm_x4(uint32_t r[4], uint32_t addr) {
    asm volatile("ldmatrix.sync.aligned.m8n8.x4.shared.b16 {%0,%1,%2,%3}, [%4];"
                 : "=r"(r[0]), "=r"(r[1]), "=r"(r[2]), "=r"(r[3]) : "r"(addr));
}
__device__ __forceinline__ void ldsm_x4t(uint32_t r[4], uint32_t addr) {
    asm volatile("ldmatrix.sync.aligned.m8n8.x4.trans.shared.b16 {%0,%1,%2,%3}, [%4];"
                 : "=r"(r[0]), "=r"(r[1]), "=r"(r[2]), "=r"(r[3]) : "r"(addr));
}
__device__ __forceinline__ void mma_f16(float c[4], const uint32_t a[4],
                                        uint32_t b0, uint32_t b1) {
    asm volatile(
        "mma.sync.aligned.m16n8k16.row.col.f32.f16.f16.f32 "
        "{%0,%1,%2,%3}, {%4,%5,%6,%7}, {%8,%9}, {%0,%1,%2,%3};"
        : "+f"(c[0]), "+f"(c[1]), "+f"(c[2]), "+f"(c[3])
        : "r"(a[0]), "r"(a[1]), "r"(a[2]), "r"(a[3]), "r"(b0), "r"(b1));
}

// ---------------------------------------------------------------------------
// fp32 -> fp16 conversion pre-pass
// ---------------------------------------------------------------------------
__global__ __launch_bounds__(256) void cvt_half_kernel(const float4* __restrict__ in,
                                                       uint2* __restrict__ out) {
    int i = blockIdx.x * 256 + threadIdx.x;
    float4 v = in[i];
    __half2 a = __floats2half2_rn(v.x, v.y);
    __half2 b = __floats2half2_rn(v.z, v.w);
    out[i] = make_uint2(*(uint32_t*)&a, *(uint32_t*)&b);
}

// ---------------------------------------------------------------------------
// FP16 tensor-core GEMM: C[M,N] = A[M,K] @ B[K,N], A/B half, C half or float.
// BM=128, BN=128, BK=32, 256 threads = 8 warps (4m x 2n), warp tile 32x64.
// mma.m16n8k16; fragments via ldmatrix from natural row-major smem tiles.
// Pads: A row stride 40 halves (ldmatrix conflict-free), B 136 halves.
// ---------------------------------------------------------------------------
#define HAK 40
#define HBN 136

template <bool HALF_OUT>
__global__ __launch_bounds__(256) void hgemm(const __half* __restrict__ A,
                                             const __half* __restrict__ B,
                                             void* __restrict__ Cv,
                                             int N, int K) {
    __shared__ __half As[2][128][HAK];
    __shared__ __half Bs[2][32][HBN];

    const int tid  = threadIdx.x;
    const int lane = tid & 31;
    const int wid  = tid >> 5;
    const int wm   = wid & 3;
    const int wn   = wid >> 2;
    const int g    = lane >> 2;
    const int q    = lane & 3;

    const int m0 = blockIdx.y * 128;
    const int n0 = blockIdx.x * 128;

    // loaders
    const int ar = tid >> 1;            // A row 0..127
    const int ac = (tid & 1) * 16;      // A half-offset 0/16
    const int bk = tid >> 4;            // B k row 0..15 (+16)
    const int bn = (tid & 15) * 8;      // B n half-offset

    float acc[2][8][4];
#pragma unroll
    for (int i = 0; i < 2; i++)
#pragma unroll
        for (int j = 0; j < 8; j++)
#pragma unroll
            for (int r = 0; r < 4; r++) acc[i][j][r] = 0.f;

    const int NC = K / 32;

    // ldmatrix base addresses (byte), lane-resolved
    const uint32_t sA = smem_u32(&As[0][0][0]);
    const uint32_t sB = smem_u32(&Bs[0][0][0]);
    const uint32_t stageA = 128 * HAK * 2;
    const uint32_t stageB = 32 * HBN * 2;
    // A: row = wm*32 + mt*16 + (l&15), col halves = ks*16 + (l>>4)*8
    const uint32_t aAddr = sA + (uint32_t)(((wm * 32 + (lane & 15)) * HAK + (lane >> 4) * 8) * 2);
    // B: row k = ks*16 + (l&15), col halves = wn*64 + nbp*16 + (l>>4)*8
    const uint32_t bAddr = sB + (uint32_t)(((lane & 15) * HBN + wn * 64 + (lane >> 4) * 8) * 2);

    uint4 pa[2], pb[2];
    auto ld_g = [&](int c) {
        const __half* Ap = A + (size_t)(m0 + ar) * K + c * 32 + ac;
        pa[0] = *(const uint4*)Ap;
        pa[1] = *(const uint4*)(Ap + 8);
        const __half* Bp = B + (size_t)(c * 32 + bk) * N + n0 + bn;
        pb[0] = *(const uint4*)Bp;
        pb[1] = *(const uint4*)(Bp + (size_t)16 * N);
    };
    auto st_s = [&](int s) {
        *(uint4*)&As[s][ar][ac]      = pa[0];
        *(uint4*)&As[s][ar][ac + 8]  = pa[1];
        *(uint4*)&Bs[s][bk][bn]      = pb[0];
        *(uint4*)&Bs[s][bk + 16][bn] = pb[1];
    };

    ld_g(0);
    st_s(0);
    __syncthreads();

    for (int c = 0; c < NC; c++) {
        const int s = c & 1;
        const bool more = (c + 1 < NC);
        if (more) ld_g(c + 1);

#pragma unroll
        for (int ks = 0; ks < 2; ks++) {
            uint32_t afr[2][4];
            ldsm_x4(afr[0], aAddr + s * stageA + ks * 32);
            ldsm_x4(afr[1], aAddr + s * stageA + ks * 32 + 16 * HAK * 2);
#pragma unroll
            for (int nbp = 0; nbp < 4; nbp++) {
                uint32_t b4[4];
                ldsm_x4t(b4, bAddr + s * stageB + ks * 16 * HBN * 2 + nbp * 32);
                mma_f16(acc[0][2 * nbp],     afr[0], b4[0], b4[1]);
                mma_f16(acc[1][2 * nbp],     afr[1], b4[0], b4[1]);
                mma_f16(acc[0][2 * nbp + 1], afr[0], b4[2], b4[3]);
                mma_f16(acc[1][2 * nbp + 1], afr[1], b4[2], b4[3]);
            }
        }

        if (more) st_s(s ^ 1);
        __syncthreads();
    }

    // epilogue
#pragma unroll
    for (int mt = 0; mt < 2; mt++) {
        int r0 = m0 + wm * 32 + mt * 16 + g;
#pragma unroll
        for (int nt = 0; nt < 8; nt++) {
            int c0 = n0 + wn * 64 + nt * 8 + q * 2;
            if (HALF_OUT) {
                __half* C = (__half*)Cv;
                __half2 v0 = __floats2half2_rn(acc[mt][nt][0], acc[mt][nt][1]);
                __half2 v1 = __floats2half2_rn(acc[mt][nt][2], acc[mt][nt][3]);
                *(__half2*)&C[(size_t)r0 * N + c0]       = v0;
                *(__half2*)&C[(size_t)(r0 + 8) * N + c0] = v1;
            } else {
                float* C = (float*)Cv;
                *(float2*)&C[(size_t)r0 * N + c0]       = make_float2(acc[mt][nt][0], acc[mt][nt][1]);
                *(float2*)&C[(size_t)(r0 + 8) * N + c0] = make_float2(acc[mt][nt][2], acc[mt][nt][3]);
            }
        }
    }
}

// ---------------------------------------------------------------------------
// Flash attention, fp16 mma.m16n8k16 + ldmatrix, causal + ALiBi.
// Block: 128 threads (4 warps) handles q-tile pair {qi, 15-qi} for one (b,h).
// Smem (halves): Qs[128][72], Ks[64][72], Vs[64][72], Ps[4][32][72]  = 55296 B
// ---------------------------------------------------------------------------
#define FST 72
#define NQT (SEQ/128)
#define FLASH_SMEM ((128*FST + 64*FST + 64*FST + 4*32*FST) * 2)

__global__ __launch_bounds__(128) void flash_f16(const __half* __restrict__ qkv,
                                                 __half* __restrict__ attn_out) {
    extern __shared__ __half smh[];
    __half* Qs = smh;                    // [qrow][d]
    __half* Ks = Qs + 128 * FST;         // [key][d]
    __half* Vs = Ks + 64 * FST;          // [key][dh]
    __half* Ps = Vs + 64 * FST;          // [warp][row][key]

    const int tid  = threadIdx.x;
    const int lane = tid & 31;
    const int w    = tid >> 5;
    const int g    = lane >> 2;
    const int q    = lane & 3;

    const int bh = blockIdx.y;
    const int b  = bh >> 4;
    const int h  = bh & 15;

    const float LOG2E  = 1.44269504088896f;
    const float scale2 = 0.125f * LOG2E;
    const float slope2 = exp2f(-0.5f * (float)(h + 1)) * LOG2E;

    const __half* qb = qkv + (size_t)b * SEQ * (3 * DIM) + h * DH;
    const __half* kb = qb + DIM;
    const __half* vb = qb + 2 * DIM;

    __half* Pw = Ps + w * 32 * FST;

    // ldmatrix lane-resolved addresses
    const uint32_t sQ = smem_u32(Qs), sK = smem_u32(Ks), sV = smem_u32(Vs),
                   sP = smem_u32(Pw);
    const int l15 = lane & 15, lhi = lane >> 4;
    // A from Qs / Pw: row = rb0 + (l&15), col = ks*16 + (l>>4)*8
    const uint32_t qA = sQ + (uint32_t)(((w * 32 + l15) * FST + lhi * 8) * 2);
    const uint32_t pA = sP + (uint32_t)((l15 * FST + lhi * 8) * 2);
    // B from Ks (non-trans): row key = nbp*16 + (l&7) + ((l>>4)<<3), col = ks*16 + ((l>>3)&1)*8
    const uint32_t kB = sK + (uint32_t)((((lane & 7) + ((lane >> 4) << 3)) * FST
                                        + ((lane >> 3) & 1) * 8) * 2);
    // B from Vs (trans): row key = ks*16 + (l&15), col = nbp*16 + (l>>4)*8
    const uint32_t vB = sV + (uint32_t)((l15 * FST + lhi * 8) * 2);

#pragma unroll 1
    for (int half_i = 0; half_i < 2; half_i++) {
        const int qi = half_i ? (NQT - 1 - blockIdx.x) : blockIdx.x;
        const int q0 = qi * 128;

        __syncthreads();

        // ---- load Q tile [128][64] halves ----
        {
            const __half* src = qb + (size_t)(q0 + tid) * (3 * DIM);
            __half* dst = Qs + tid * FST;
#pragma unroll
            for (int c = 0; c < 8; c++)
                *(uint4*)(dst + c * 8) = *(const uint4*)(src + c * 8);
        }

        float o[2][8][4];
        float mprev[2][2], lrun[2][2];
#pragma unroll
        for (int mt = 0; mt < 2; mt++) {
            mprev[mt][0] = mprev[mt][1] = -1e30f;
            lrun[mt][0]  = lrun[mt][1]  = 0.f;
#pragma unroll
            for (int nt = 0; nt < 8; nt++)
#pragma unroll
                for (int r = 0; r < 4; r++) o[mt][nt][r] = 0.f;
        }

        const int nkt = 2 * qi + 2;
        const int wrow_min = q0 + w * 32;
        const int wrow_max = wrow_min + 31;

        for (int kt = 0; kt < nkt; kt++) {
            const int k0 = kt * 64;
            __syncthreads();

            // ---- load K,V tiles [64][64] halves each ----
            {
                int r  = tid >> 1;
                int c0 = (tid & 1) * 32;
                const __half* ksrc = kb + (size_t)(k0 + r) * (3 * DIM) + c0;
                const __half* vsrc = vb + (size_t)(k0 + r) * (3 * DIM) + c0;
                __half* kdst = Ks + r * FST + c0;
                __half* vdst = Vs + r * FST + c0;
#pragma unroll
                for (int c = 0; c < 4; c++) {
                    *(uint4*)(kdst + c * 8) = *(const uint4*)(ksrc + c * 8);
                    *(uint4*)(vdst + c * 8) = *(const uint4*)(vsrc + c * 8);
                }
            }
            __syncthreads();

            if (k0 > wrow_max) continue;

            // ---- S = Q @ K^T ----
            float s[2][8][4];
#pragma unroll
            for (int mt = 0; mt < 2; mt++)
#pragma unroll
                for (int nt = 0; nt < 8; nt++)
#pragma unroll
                    for (int r = 0; r < 4; r++) s[mt][nt][r] = 0.f;

#pragma unroll
            for (int ks = 0; ks < 4; ks++) {
                uint32_t afr[2][4];
                ldsm_x4(afr[0], qA + ks * 32);
                ldsm_x4(afr[1], qA + ks * 32 + 16 * FST * 2);
#pragma unroll
                for (int nbp = 0; nbp < 4; nbp++) {
                    uint32_t b4[4];
                    ldsm_x4(b4, kB + nbp * 16 * FST * 2 + ks * 32);
                    mma_f16(s[0][2 * nbp],     afr[0], b4[0], b4[1]);
                    mma_f16(s[1][2 * nbp],     afr[1], b4[0], b4[1]);
                    mma_f16(s[0][2 * nbp + 1], afr[0], b4[2], b4[3]);
                    mma_f16(s[1][2 * nbp + 1], afr[1], b4[2], b4[3]);
                }
            }

            // ---- bias + mask + online softmax (base-2) ----
            const bool need_mask = (k0 + 63 > wrow_min);
#pragma unroll
            for (int mt = 0; mt < 2; mt++) {
                const int r0 = wrow_min + mt * 16 + g;
                const int r1 = r0 + 8;
                float mx0 = -1e30f, mx1 = -1e30f;
#pragma unroll
                for (int nt = 0; nt < 8; nt++) {
#pragma unroll
                    for (int jj = 0; jj < 2; jj++) {
                        int col = k0 + nt * 8 + q * 2 + jj;
                        float bias = slope2 * (float)col;
                        float v0 = fmaf(s[mt][nt][jj],     scale2, bias);
                        float v1 = fmaf(s[mt][nt][2 + jj], scale2, bias);
                        if (need_mask) {
                            if (col > r0) v0 = -1e30f;
                            if (col > r1) v1 = -1e30f;
                        }
                        s[mt][nt][jj]     = v0;
                        s[mt][nt][2 + jj] = v1;
                        mx0 = fmaxf(mx0, v0);
                        mx1 = fmaxf(mx1, v1);
                    }
                }
                mx0 = fmaxf(mx0, __shfl_xor_sync(0xffffffffu, mx0, 1));
                mx0 = fmaxf(mx0, __shfl_xor_sync(0xffffffffu, mx0, 2));
                mx1 = fmaxf(mx1, __shfl_xor_sync(0xffffffffu, mx1, 1));
                mx1 = fmaxf(mx1, __shfl_xor_sync(0xffffffffu, mx1, 2));

                float mn0 = fmaxf(mprev[mt][0], mx0);
                float mn1 = fmaxf(mprev[mt][1], mx1);
                float sum0 = 0.f, sum1 = 0.f;
#pragma unroll
                for (int nt = 0; nt < 8; nt++) {
#pragma unroll
                    for (int jj = 0; jj < 2; jj++) {
                        float p0 = exp2f(s[mt][nt][jj]     - mn0);
                        float p1 = exp2f(s[mt][nt][2 + jj] - mn1);
                        s[mt][nt][jj]     = p0;
                        s[mt][nt][2 + jj] = p1;
                        sum0 += p0;
                        sum1 += p1;
                    }
                }
                sum0 += __shfl_xor_sync(0xffffffffu, sum0, 1);
                sum0 += __shfl_xor_sync(0xffffffffu, sum0, 2);
                sum1 += __shfl_xor_sync(0xffffffffu, sum1, 1);
                sum1 += __shfl_xor_sync(0xffffffffu, sum1, 2);

                float al0 = exp2f(mprev[mt][0] - mn0);
                float al1 = exp2f(mprev[mt][1] - mn1);
                lrun[mt][0] = lrun[mt][0] * al0 + sum0;
                lrun[mt][1] = lrun[mt][1] * al1 + sum1;
                mprev[mt][0] = mn0;
                mprev[mt][1] = mn1;
#pragma unroll
                for (int nt = 0; nt < 8; nt++) {
                    o[mt][nt][0] *= al0;
                    o[mt][nt][1] *= al0;
                    o[mt][nt][2] *= al1;
                    o[mt][nt][3] *= al1;
                }

                // write P tile (per-warp smem) as half2
#pragma unroll
                for (int nt = 0; nt < 8; nt++) {
                    *(__half2*)&Pw[(mt * 16 + g)     * FST + nt * 8 + q * 2] =
                        __floats2half2_rn(s[mt][nt][0], s[mt][nt][1]);
                    *(__half2*)&Pw[(mt * 16 + g + 8) * FST + nt * 8 + q * 2] =
                        __floats2half2_rn(s[mt][nt][2], s[mt][nt][3]);
                }
            }
            __syncwarp();

            // ---- O += P @ V ----
#pragma unroll
            for (int ks = 0; ks < 4; ks++) {
                uint32_t afr[2][4];
                ldsm_x4(afr[0], pA + ks * 32);
                ldsm_x4(afr[1], pA + ks * 32 + 16 * FST * 2);
#pragma unroll
                for (int nbp = 0; nbp < 4; nbp++) {
                    uint32_t b4[4];
                    ldsm_x4t(b4, vB + ks * 16 * FST * 2 + nbp * 32);
                    mma_f16(o[0][2 * nbp],     afr[0], b4[0], b4[1]);
                    mma_f16(o[1][2 * nbp],     afr[1], b4[0], b4[1]);
                    mma_f16(o[0][2 * nbp + 1], afr[0], b4[2], b4[3]);
                    mma_f16(o[1][2 * nbp + 1], afr[1], b4[2], b4[3]);
                }
            }
        }

        // ---- epilogue: normalize, store half ----
#pragma unroll
        for (int mt = 0; mt < 2; mt++) {
            float inv0 = 1.f / lrun[mt][0];
            float inv1 = 1.f / lrun[mt][1];
            int r0 = q0 + w * 32 + mt * 16 + g;
#pragma unroll
            for (int nt = 0; nt < 8; nt++) {
                int c = h * DH + nt * 8 + q * 2;
                *(__half2*)&attn_out[(size_t)(b * SEQ + r0) * DIM + c] =
                    __floats2half2_rn(o[mt][nt][0] * inv0, o[mt][nt][1] * inv0);
                *(__half2*)&attn_out[(size_t)(b * SEQ + r0 + 8) * DIM + c] =
                    __floats2half2_rn(o[mt][nt][2] * inv1, o[mt][nt][3] * inv1);
            }
        }
    }
}

// ---------------------------------------------------------------------------
extern "C" void kernel_launch(void* const* d_in, const int* in_sizes, int n_in,
                              void* d_out, int out_size) {
    const float* x      = (const float*)d_in[0];   // [2,2048,1024]
    const float* w_qkv  = (const float*)d_in[1];   // [1024,3072]
    const float* w_proj = (const float*)d_in[2];   // [1024,1024]
    float* out = (float*)d_out;                    // [2,2048,1024]

    __half *xh, *wqkvh, *wprojh, *qkv, *attn;
    cudaGetSymbolAddress((void**)&xh, g_xh);
    cudaGetSymbolAddress((void**)&wqkvh, g_wqkv_h);
    cudaGetSymbolAddress((void**)&wprojh, g_wproj_h);
    cudaGetSymbolAddress((void**)&qkv, g_qkv);
    cudaGetSymbolAddress((void**)&attn, g_attn);

    cudaFuncSetAttribute(flash_f16, cudaFuncAttributeMaxDynamicSharedMemorySize,
                         (int)FLASH_SMEM);

    // 0) convert inputs to half
    cvt_half_kernel<<<(MTOT * DIM) / 1024, 256>>>((const float4*)x, (uint2*)xh);
    cvt_half_kernel<<<(DIM * 3 * DIM) / 1024, 256>>>((const float4*)w_qkv, (uint2*)wqkvh);
    cvt_half_kernel<<<(DIM * DIM) / 1024, 256>>>((const float4*)w_proj, (uint2*)wprojh);

    // 1) qkv = x @ w_qkv  (half out)
    hgemm<true><<<dim3(3 * DIM / 128, MTOT / 128), 256>>>(xh, wqkvh, qkv, 3 * DIM, DIM);

    // 2) attention (balanced q-tile pairs), half in/out
    flash_f16<<<dim3(NQT / 2, BATCH * HEADS), 128, FLASH_SMEM>>>(qkv, attn);

    // 3) out = attn @ w_proj  (float out)
    hgemm<false><<<dim3(DIM / 128, MTOT / 128), 256>>>(attn, wprojh, out, DIM, DIM);
}

// round 11
// speedup vs baseline: 2.0427x; 1.3669x over previous
#include <cuda_runtime.h>
#include <cuda_fp16.h>
#include <math.h>
#include <stdint.h>

// Problem constants
#define BATCH 2
#define SEQ   2048
#define DIM   1024
#define HEADS 16
#define DH    64
#define MTOT  (BATCH*SEQ)          // 4096 rows

// Scratch (allocation-free rule: __device__ globals)
__device__ __half g_xh[(size_t)MTOT * DIM];          // x as half
__device__ __half g_wqkv_h[(size_t)DIM * 3 * DIM];   // w_qkv as half [1024][3072]
__device__ __half g_wproj_h[(size_t)DIM * DIM];      // w_proj as half
__device__ __half g_qkv[(size_t)MTOT * 3 * DIM];     // qkv as half
__device__ __half g_attn[(size_t)MTOT * DIM];        // attn out as half

// ---------------------------------------------------------------------------
// PTX helpers
// ---------------------------------------------------------------------------
__device__ __forceinline__ uint32_t smem_u32(const void* p) {
    uint32_t a;
    asm("{ .reg .u64 t; cvta.to.shared.u64 t, %1; cvt.u32.u64 %0, t; }" : "=r"(a) : "l"(p));
    return a;
}

__device__ __forceinline__ void ldsm_x4(uint32_t r[4], uint32_t addr) {
    asm volatile("ldmatrix.sync.aligned.m8n8.x4.shared.b16 {%0,%1,%2,%3}, [%4];"
                 : "=r"(r[0]), "=r"(r[1]), "=r"(r[2]), "=r"(r[3]) : "r"(addr));
}
__device__ __forceinline__ void ldsm_x4t(uint32_t r[4], uint32_t addr) {
    asm volatile("ldmatrix.sync.aligned.m8n8.x4.trans.shared.b16 {%0,%1,%2,%3}, [%4];"
                 : "=r"(r[0]), "=r"(r[1]), "=r"(r[2]), "=r"(r[3]) : "r"(addr));
}
__device__ __forceinline__ void mma_f16(float c[4], const uint32_t a[4],
                                        uint32_t b0, uint32_t b1) {
    asm volatile(
        "mma.sync.aligned.m16n8k16.row.col.f32.f16.f16.f32 "
        "{%0,%1,%2,%3}, {%4,%5,%6,%7}, {%8,%9}, {%0,%1,%2,%3};"
        : "+f"(c[0]), "+f"(c[1]), "+f"(c[2]), "+f"(c[3])
        : "r"(a[0]), "r"(a[1]), "r"(a[2]), "r"(a[3]), "r"(b0), "r"(b1));
}

#define CP_A16(dst, src) \
    asm volatile("cp.async.cg.shared.global [%0], [%1], 16;" :: "r"(dst), "l"(src))
#define CP_COMMIT() asm volatile("cp.async.commit_group;" ::: "memory")
#define CP_WAIT(n)  asm volatile("cp.async.wait_group %0;" :: "n"(n) : "memory")

// ---------------------------------------------------------------------------
// fp32 -> fp16 conversion pre-pass
// ---------------------------------------------------------------------------
__global__ __launch_bounds__(256) void cvt_half_kernel(const float4* __restrict__ in,
                                                       uint2* __restrict__ out) {
    int i = blockIdx.x * 256 + threadIdx.x;
    float4 v = in[i];
    __half2 a = __floats2half2_rn(v.x, v.y);
    __half2 b = __floats2half2_rn(v.z, v.w);
    out[i] = make_uint2(*(uint32_t*)&a, *(uint32_t*)&b);
}

// ---------------------------------------------------------------------------
// FP16 tensor-core GEMM v2: C[M,N] = A[M,K] @ B[K,N].
// BM=BN=128, BK=32; 128 threads = 4 warps (2m x 2n), warp tile 64x64.
// cp.async double-buffered loads; fragments via ldmatrix.
// ---------------------------------------------------------------------------
#define HAK 40
#define HBN 136

template <bool HALF_OUT>
__global__ __launch_bounds__(128, 2) void hgemm(const __half* __restrict__ A,
                                                const __half* __restrict__ B,
                                                void* __restrict__ Cv,
                                                int N, int K) {
    __shared__ __half As[2][128][HAK];
    __shared__ __half Bs[2][32][HBN];

    const int tid  = threadIdx.x;
    const int lane = tid & 31;
    const int wid  = tid >> 5;
    const int wm   = wid & 1;        // m offset wm*64
    const int wn   = wid >> 1;       // n offset wn*64
    const int g    = lane >> 2;
    const int q    = lane & 3;

    const int m0 = blockIdx.y * 128;
    const int n0 = blockIdx.x * 128;

    float acc[4][8][4];
#pragma unroll
    for (int i = 0; i < 4; i++)
#pragma unroll
        for (int j = 0; j < 8; j++)
#pragma unroll
            for (int r = 0; r < 4; r++) acc[i][j][r] = 0.f;

    const int NC = K / 32;

    const uint32_t aBase = smem_u32(&As[0][0][0]);
    const uint32_t bBase = smem_u32(&Bs[0][0][0]);
    const uint32_t stageA = 128 * HAK * 2;
    const uint32_t stageB = 32 * HBN * 2;

    // ldmatrix lane-resolved addresses
    const int l15 = lane & 15, lhi = lane >> 4;
    const uint32_t aAddr = aBase + (uint32_t)(((wm * 64 + l15) * HAK + lhi * 8) * 2);
    const uint32_t bAddr = bBase + (uint32_t)((l15 * HBN + wn * 64 + lhi * 8) * 2);

    // cp.async loaders
    const __half* Arow = A + (size_t)(m0 + tid) * K;           // thread = row
    auto ld_async = [&](int c, int s) {
        // A tile: 128 rows x 32 halves; thread tid -> row tid, 4 x 16B
        const __half* asrc = Arow + c * 32;
        uint32_t adst = aBase + s * stageA + (uint32_t)(tid * HAK * 2);
#pragma unroll
        for (int i = 0; i < 4; i++)
            CP_A16(adst + i * 16, asrc + i * 8);
        // B tile: 32 rows x 128 halves = 512 x 16B chunks
#pragma unroll
        for (int i = 0; i < 4; i++) {
            int idx = tid + i * 128;
            int row = idx >> 4, ch = idx & 15;
            const __half* bsrc = B + (size_t)(c * 32 + row) * N + n0 + ch * 8;
            uint32_t bdst = bBase + s * stageB + (uint32_t)((row * HBN + ch * 8) * 2);
            CP_A16(bdst, bsrc);
        }
    };

    ld_async(0, 0);
    CP_COMMIT();

    for (int c = 0; c < NC; c++) {
        const int s = c & 1;
        if (c + 1 < NC) {
            ld_async(c + 1, s ^ 1);
            CP_COMMIT();
            CP_WAIT(1);
        } else {
            CP_WAIT(0);
        }
        __syncthreads();

#pragma unroll
        for (int ks = 0; ks < 2; ks++) {
            uint32_t afr[4][4];
#pragma unroll
            for (int mt = 0; mt < 4; mt++)
                ldsm_x4(afr[mt], aAddr + s * stageA + ks * 32 + mt * (16 * HAK * 2));
#pragma unroll
            for (int nbp = 0; nbp < 4; nbp++) {
                uint32_t b4[4];
                ldsm_x4t(b4, bAddr + s * stageB + ks * (16 * HBN * 2) + nbp * 32);
#pragma unroll
                for (int mt = 0; mt < 4; mt++) {
                    mma_f16(acc[mt][2 * nbp],     afr[mt], b4[0], b4[1]);
                    mma_f16(acc[mt][2 * nbp + 1], afr[mt], b4[2], b4[3]);
                }
            }
        }
        __syncthreads();
    }

    // epilogue: warp writes its 64x64 tile
#pragma unroll
    for (int mt = 0; mt < 4; mt++) {
        int r0 = m0 + wm * 64 + mt * 16 + g;
#pragma unroll
        for (int nt = 0; nt < 8; nt++) {
            int c0 = n0 + wn * 64 + nt * 8 + q * 2;
            if (HALF_OUT) {
                __half* C = (__half*)Cv;
                *(__half2*)&C[(size_t)r0 * N + c0] =
                    __floats2half2_rn(acc[mt][nt][0], acc[mt][nt][1]);
                *(__half2*)&C[(size_t)(r0 + 8) * N + c0] =
                    __floats2half2_rn(acc[mt][nt][2], acc[mt][nt][3]);
            } else {
                float* C = (float*)Cv;
                *(float2*)&C[(size_t)r0 * N + c0]       = make_float2(acc[mt][nt][0], acc[mt][nt][1]);
                *(float2*)&C[(size_t)(r0 + 8) * N + c0] = make_float2(acc[mt][nt][2], acc[mt][nt][3]);
            }
        }
    }
}

// ---------------------------------------------------------------------------
// Flash attention, fp16 mma.m16n8k16 + ldmatrix, causal + ALiBi.
// One CTA per (q-tile of 128 rows, b, h); 512 CTAs, large tiles first.
// ---------------------------------------------------------------------------
#define FST 72
#define NQT (SEQ/128)
#define FLASH_SMEM ((128*FST + 64*FST + 64*FST + 4*32*FST) * 2)

__global__ __launch_bounds__(128) void flash_f16(const __half* __restrict__ qkv,
                                                 __half* __restrict__ attn_out) {
    extern __shared__ __half smh[];
    __half* Qs = smh;                    // [qrow][d]
    __half* Ks = Qs + 128 * FST;         // [key][d]
    __half* Vs = Ks + 64 * FST;          // [key][dh]
    __half* Ps = Vs + 64 * FST;          // [warp][row][key]

    const int tid  = threadIdx.x;
    const int lane = tid & 31;
    const int w    = tid >> 5;
    const int g    = lane >> 2;
    const int q    = lane & 3;

    const int bh = blockIdx.y;
    const int b  = bh >> 4;
    const int h  = bh & 15;

    const float LOG2E  = 1.44269504088896f;
    const float scale2 = 0.125f * LOG2E;
    const float slope2 = exp2f(-0.5f * (float)(h + 1)) * LOG2E;

    const __half* qb = qkv + (size_t)b * SEQ * (3 * DIM) + h * DH;
    const __half* kb = qb + DIM;
    const __half* vb = qb + 2 * DIM;

    __half* Pw = Ps + w * 32 * FST;

    const uint32_t sQ = smem_u32(Qs), sK = smem_u32(Ks), sV = smem_u32(Vs),
                   sP = smem_u32(Pw);
    const int l15 = lane & 15, lhi = lane >> 4;
    const uint32_t qA = sQ + (uint32_t)(((w * 32 + l15) * FST + lhi * 8) * 2);
    const uint32_t pA = sP + (uint32_t)((l15 * FST + lhi * 8) * 2);
    const uint32_t kB = sK + (uint32_t)((((lane & 7) + ((lane >> 4) << 3)) * FST
                                        + ((lane >> 3) & 1) * 8) * 2);
    const uint32_t vB = sV + (uint32_t)((l15 * FST + lhi * 8) * 2);

    const int qi = NQT - 1 - blockIdx.x;    // big tiles first
    const int q0 = qi * 128;

    // ---- load Q tile [128][64] halves ----
    {
        const __half* src = qb + (size_t)(q0 + tid) * (3 * DIM);
        __half* dst = Qs + tid * FST;
#pragma unroll
        for (int c = 0; c < 8; c++)
            *(uint4*)(dst + c * 8) = *(const uint4*)(src + c * 8);
    }

    float o[2][8][4];
    float mprev[2][2], lrun[2][2];
#pragma unroll
    for (int mt = 0; mt < 2; mt++) {
        mprev[mt][0] = mprev[mt][1] = -1e30f;
        lrun[mt][0]  = lrun[mt][1]  = 0.f;
#pragma unroll
        for (int nt = 0; nt < 8; nt++)
#pragma unroll
            for (int r = 0; r < 4; r++) o[mt][nt][r] = 0.f;
    }

    const int nkt = 2 * qi + 2;
    const int wrow_min = q0 + w * 32;
    const int wrow_max = wrow_min + 31;

    for (int kt = 0; kt < nkt; kt++) {
        const int k0 = kt * 64;
        __syncthreads();

        // ---- load K,V tiles [64][64] halves each ----
        {
            int r  = tid >> 1;
            int c0 = (tid & 1) * 32;
            const __half* ksrc = kb + (size_t)(k0 + r) * (3 * DIM) + c0;
            const __half* vsrc = vb + (size_t)(k0 + r) * (3 * DIM) + c0;
            __half* kdst = Ks + r * FST + c0;
            __half* vdst = Vs + r * FST + c0;
#pragma unroll
            for (int c = 0; c < 4; c++) {
                *(uint4*)(kdst + c * 8) = *(const uint4*)(ksrc + c * 8);
                *(uint4*)(vdst + c * 8) = *(const uint4*)(vsrc + c * 8);
            }
        }
        __syncthreads();

        if (k0 > wrow_max) continue;

        // ---- S = Q @ K^T ----
        float s[2][8][4];
#pragma unroll
        for (int mt = 0; mt < 2; mt++)
#pragma unroll
            for (int nt = 0; nt < 8; nt++)
#pragma unroll
                for (int r = 0; r < 4; r++) s[mt][nt][r] = 0.f;

#pragma unroll
        for (int ks = 0; ks < 4; ks++) {
            uint32_t afr[2][4];
            ldsm_x4(afr[0], qA + ks * 32);
            ldsm_x4(afr[1], qA + ks * 32 + 16 * FST * 2);
#pragma unroll
            for (int nbp = 0; nbp < 4; nbp++) {
                uint32_t b4[4];
                ldsm_x4(b4, kB + nbp * 16 * FST * 2 + ks * 32);
                mma_f16(s[0][2 * nbp],     afr[0], b4[0], b4[1]);
                mma_f16(s[1][2 * nbp],     afr[1], b4[0], b4[1]);
                mma_f16(s[0][2 * nbp + 1], afr[0], b4[2], b4[3]);
                mma_f16(s[1][2 * nbp + 1], afr[1], b4[2], b4[3]);
            }
        }

        // ---- bias + mask + online softmax (base-2) ----
        const bool need_mask = (k0 + 63 > wrow_min);
#pragma unroll
        for (int mt = 0; mt < 2; mt++) {
            const int r0 = wrow_min + mt * 16 + g;
            const int r1 = r0 + 8;
            float mx0 = -1e30f, mx1 = -1e30f;
#pragma unroll
            for (int nt = 0; nt < 8; nt++) {
#pragma unroll
                for (int jj = 0; jj < 2; jj++) {
                    int col = k0 + nt * 8 + q * 2 + jj;
                    float bias = slope2 * (float)col;
                    float v0 = fmaf(s[mt][nt][jj],     scale2, bias);
                    float v1 = fmaf(s[mt][nt][2 + jj], scale2, bias);
                    if (need_mask) {
                        if (col > r0) v0 = -1e30f;
                        if (col > r1) v1 = -1e30f;
                    }
                    s[mt][nt][jj]     = v0;
                    s[mt][nt][2 + jj] = v1;
                    mx0 = fmaxf(mx0, v0);
                    mx1 = fmaxf(mx1, v1);
                }
            }
            mx0 = fmaxf(mx0, __shfl_xor_sync(0xffffffffu, mx0, 1));
            mx0 = fmaxf(mx0, __shfl_xor_sync(0xffffffffu, mx0, 2));
            mx1 = fmaxf(mx1, __shfl_xor_sync(0xffffffffu, mx1, 1));
            mx1 = fmaxf(mx1, __shfl_xor_sync(0xffffffffu, mx1, 2));

            float mn0 = fmaxf(mprev[mt][0], mx0);
            float mn1 = fmaxf(mprev[mt][1], mx1);
            float sum0 = 0.f, sum1 = 0.f;
#pragma unroll
            for (int nt = 0; nt < 8; nt++) {
#pragma unroll
                for (int jj = 0; jj < 2; jj++) {
                    float p0 = exp2f(s[mt][nt][jj]     - mn0);
                    float p1 = exp2f(s[mt][nt][2 + jj] - mn1);
                    s[mt][nt][jj]     = p0;
                    s[mt][nt][2 + jj] = p1;
                    sum0 += p0;
                    sum1 += p1;
                }
            }
            sum0 += __shfl_xor_sync(0xffffffffu, sum0, 1);
            sum0 += __shfl_xor_sync(0xffffffffu, sum0, 2);
            sum1 += __shfl_xor_sync(0xffffffffu, sum1, 1);
            sum1 += __shfl_xor_sync(0xffffffffu, sum1, 2);

            float al0 = exp2f(mprev[mt][0] - mn0);
            float al1 = exp2f(mprev[mt][1] - mn1);
            lrun[mt][0] = lrun[mt][0] * al0 + sum0;
            lrun[mt][1] = lrun[mt][1] * al1 + sum1;
            mprev[mt][0] = mn0;
            mprev[mt][1] = mn1;
#pragma unroll
            for (int nt = 0; nt < 8; nt++) {
                o[mt][nt][0] *= al0;
                o[mt][nt][1] *= al0;
                o[mt][nt][2] *= al1;
                o[mt][nt][3] *= al1;
            }

#pragma unroll
            for (int nt = 0; nt < 8; nt++) {
                *(__half2*)&Pw[(mt * 16 + g)     * FST + nt * 8 + q * 2] =
                    __floats2half2_rn(s[mt][nt][0], s[mt][nt][1]);
                *(__half2*)&Pw[(mt * 16 + g + 8) * FST + nt * 8 + q * 2] =
                    __floats2half2_rn(s[mt][nt][2], s[mt][nt][3]);
            }
        }
        __syncwarp();

        // ---- O += P @ V ----
#pragma unroll
        for (int ks = 0; ks < 4; ks++) {
            uint32_t afr[2][4];
            ldsm_x4(afr[0], pA + ks * 32);
            ldsm_x4(afr[1], pA + ks * 32 + 16 * FST * 2);
#pragma unroll
            for (int nbp = 0; nbp < 4; nbp++) {
                uint32_t b4[4];
                ldsm_x4t(b4, vB + ks * 16 * FST * 2 + nbp * 32);
                mma_f16(o[0][2 * nbp],     afr[0], b4[0], b4[1]);
                mma_f16(o[1][2 * nbp],     afr[1], b4[0], b4[1]);
                mma_f16(o[0][2 * nbp + 1], afr[0], b4[2], b4[3]);
                mma_f16(o[1][2 * nbp + 1], afr[1], b4[2], b4[3]);
            }
        }
    }

    // ---- epilogue: normalize, store half ----
#pragma unroll
    for (int mt = 0; mt < 2; mt++) {
        float inv0 = 1.f / lrun[mt][0];
        float inv1 = 1.f / lrun[mt][1];
        int r0 = q0 + w * 32 + mt * 16 + g;
#pragma unroll
        for (int nt = 0; nt < 8; nt++) {
            int c = h * DH + nt * 8 + q * 2;
            *(__half2*)&attn_out[(size_t)(b * SEQ + r0) * DIM + c] =
                __floats2half2_rn(o[mt][nt][0] * inv0, o[mt][nt][1] * inv0);
            *(__half2*)&attn_out[(size_t)(b * SEQ + r0 + 8) * DIM + c] =
                __floats2half2_rn(o[mt][nt][2] * inv1, o[mt][nt][3] * inv1);
        }
    }
}

// ---------------------------------------------------------------------------
extern "C" void kernel_launch(void* const* d_in, const int* in_sizes, int n_in,
                              void* d_out, int out_size) {
    const float* x      = (const float*)d_in[0];   // [2,2048,1024]
    const float* w_qkv  = (const float*)d_in[1];   // [1024,3072]
    const float* w_proj = (const float*)d_in[2];   // [1024,1024]
    float* out = (float*)d_out;                    // [2,2048,1024]

    __half *xh, *wqkvh, *wprojh, *qkv, *attn;
    cudaGetSymbolAddress((void**)&xh, g_xh);
    cudaGetSymbolAddress((void**)&wqkvh, g_wqkv_h);
    cudaGetSymbolAddress((void**)&wprojh, g_wproj_h);
    cudaGetSymbolAddress((void**)&qkv, g_qkv);
    cudaGetSymbolAddress((void**)&attn, g_attn);

    cudaFuncSetAttribute(flash_f16, cudaFuncAttributeMaxDynamicSharedMemorySize,
                         (int)FLASH_SMEM);

    // 0) convert inputs to half
    cvt_half_kernel<<<(MTOT * DIM) / 1024, 256>>>((const float4*)x, (uint2*)xh);
    cvt_half_kernel<<<(DIM * 3 * DIM) / 1024, 256>>>((const float4*)w_qkv, (uint2*)wqkvh);
    cvt_half_kernel<<<(DIM * DIM) / 1024, 256>>>((const float4*)w_proj, (uint2*)wprojh);

    // 1) qkv = x @ w_qkv  (half out)
    hgemm<true><<<dim3(3 * DIM / 128, MTOT / 128), 128>>>(xh, wqkvh, qkv, 3 * DIM, DIM);

    // 2) attention: one CTA per (q-tile, b, h), big tiles first
    flash_f16<<<dim3(NQT, BATCH * HEADS), 128, FLASH_SMEM>>>(qkv, attn);

    // 3) out = attn @ w_proj  (float out)
    hgemm<false><<<dim3(DIM / 128, MTOT / 128), 128>>>(attn, wprojh, out, DIM, DIM);
}

// round 12
// speedup vs baseline: 2.0772x; 1.0169x over previous
#include <cuda_runtime.h>
#include <cuda_fp16.h>
#include <math.h>
#include <stdint.h>

// Problem constants
#define BATCH 2
#define SEQ   2048
#define DIM   1024
#define HEADS 16
#define DH    64
#define MTOT  (BATCH*SEQ)          // 4096 rows

// Scratch (allocation-free rule: __device__ globals)
__device__ __half g_xh[(size_t)MTOT * DIM];
__device__ __half g_wqkv_h[(size_t)DIM * 3 * DIM];
__device__ __half g_wproj_h[(size_t)DIM * DIM];
__device__ __half g_qkv[(size_t)MTOT * 3 * DIM];
__device__ __half g_attn[(size_t)MTOT * DIM];

// ---------------------------------------------------------------------------
// PTX helpers
// ---------------------------------------------------------------------------
__device__ __forceinline__ uint32_t smem_u32(const void* p) {
    uint32_t a;
    asm("{ .reg .u64 t; cvta.to.shared.u64 t, %1; cvt.u32.u64 %0, t; }" : "=r"(a) : "l"(p));
    return a;
}

__device__ __forceinline__ void ldsm_x4(uint32_t r[4], uint32_t addr) {
    asm volatile("ldmatrix.sync.aligned.m8n8.x4.shared.b16 {%0,%1,%2,%3}, [%4];"
                 : "=r"(r[0]), "=r"(r[1]), "=r"(r[2]), "=r"(r[3]) : "r"(addr));
}
__device__ __forceinline__ void ldsm_x4t(uint32_t r[4], uint32_t addr) {
    asm volatile("ldmatrix.sync.aligned.m8n8.x4.trans.shared.b16 {%0,%1,%2,%3}, [%4];"
                 : "=r"(r[0]), "=r"(r[1]), "=r"(r[2]), "=r"(r[3]) : "r"(addr));
}
__device__ __forceinline__ void mma_f16(float c[4], const uint32_t a[4],
                                        uint32_t b0, uint32_t b1) {
    asm volatile(
        "mma.sync.aligned.m16n8k16.row.col.f32.f16.f16.f32 "
        "{%0,%1,%2,%3}, {%4,%5,%6,%7}, {%8,%9}, {%0,%1,%2,%3};"
        : "+f"(c[0]), "+f"(c[1]), "+f"(c[2]), "+f"(c[3])
        : "r"(a[0]), "r"(a[1]), "r"(a[2]), "r"(a[3]), "r"(b0), "r"(b1));
}
__device__ __forceinline__ float ex2f(float x) {
    float r;
    asm("ex2.approx.ftz.f32 %0, %1;" : "=f"(r) : "f"(x));
    return r;
}

#define CP_A16(dst, src) \
    asm volatile("cp.async.cg.shared.global [%0], [%1], 16;" :: "r"(dst), "l"(src))
#define CP_COMMIT() asm volatile("cp.async.commit_group;" ::: "memory")
#define CP_WAIT(n)  asm volatile("cp.async.wait_group %0;" :: "n"(n) : "memory")

// ---------------------------------------------------------------------------
// fp32 -> fp16 conversion pre-pass
// ---------------------------------------------------------------------------
__global__ __launch_bounds__(256) void cvt_half_kernel(const float4* __restrict__ in,
                                                       uint2* __restrict__ out) {
    int i = blockIdx.x * 256 + threadIdx.x;
    float4 v = in[i];
    __half2 a = __floats2half2_rn(v.x, v.y);
    __half2 b = __floats2half2_rn(v.z, v.w);
    out[i] = make_uint2(*(uint32_t*)&a, *(uint32_t*)&b);
}

// ---------------------------------------------------------------------------
// FP16 tensor-core GEMM v3: 3-stage cp.async pipeline.
// BM=BN=128, BK=32; 128 threads = 4 warps (2m x 2n), warp tile 64x64.
// ---------------------------------------------------------------------------
#define HAK 40
#define HBN 136
#define NST 3

template <bool HALF_OUT>
__global__ __launch_bounds__(128, 2) void hgemm(const __half* __restrict__ A,
                                                const __half* __restrict__ B,
                                                void* __restrict__ Cv,
                                                int N, int K) {
    __shared__ __half As[NST][128][HAK];
    __shared__ __half Bs[NST][32][HBN];

    const int tid  = threadIdx.x;
    const int lane = tid & 31;
    const int wid  = tid >> 5;
    const int wm   = wid & 1;
    const int wn   = wid >> 1;
    const int g    = lane >> 2;
    const int q    = lane & 3;

    const int m0 = blockIdx.y * 128;
    const int n0 = blockIdx.x * 128;

    float acc[4][8][4];
#pragma unroll
    for (int i = 0; i < 4; i++)
#pragma unroll
        for (int j = 0; j < 8; j++)
#pragma unroll
            for (int r = 0; r < 4; r++) acc[i][j][r] = 0.f;

    const int NC = K / 32;

    const uint32_t aBase = smem_u32(&As[0][0][0]);
    const uint32_t bBase = smem_u32(&Bs[0][0][0]);
    const uint32_t stageA = 128 * HAK * 2;
    const uint32_t stageB = 32 * HBN * 2;

    const int l15 = lane & 15, lhi = lane >> 4;
    const uint32_t aAddr = aBase + (uint32_t)(((wm * 64 + l15) * HAK + lhi * 8) * 2);
    const uint32_t bAddr = bBase + (uint32_t)((l15 * HBN + wn * 64 + lhi * 8) * 2);

    const __half* Arow = A + (size_t)(m0 + tid) * K;
    auto ld_async = [&](int c, int s) {
        const __half* asrc = Arow + c * 32;
        uint32_t adst = aBase + s * stageA + (uint32_t)(tid * HAK * 2);
#pragma unroll
        for (int i = 0; i < 4; i++)
            CP_A16(adst + i * 16, asrc + i * 8);
#pragma unroll
        for (int i = 0; i < 4; i++) {
            int idx = tid + i * 128;
            int row = idx >> 4, ch = idx & 15;
            const __half* bsrc = B + (size_t)(c * 32 + row) * N + n0 + ch * 8;
            uint32_t bdst = bBase + s * stageB + (uint32_t)((row * HBN + ch * 8) * 2);
            CP_A16(bdst, bsrc);
        }
    };

    ld_async(0, 0); CP_COMMIT();
    ld_async(1, 1); CP_COMMIT();

    for (int c = 0; c < NC; c++) {
        const int s = c % NST;
        if (c + 1 < NC) { CP_WAIT(1); } else { CP_WAIT(0); }
        __syncthreads();
        if (c + 2 < NC) { ld_async(c + 2, (c + 2) % NST); CP_COMMIT(); }

#pragma unroll
        for (int ks = 0; ks < 2; ks++) {
            uint32_t afr[4][4];
#pragma unroll
            for (int mt = 0; mt < 4; mt++)
                ldsm_x4(afr[mt], aAddr + s * stageA + ks * 32 + mt * (16 * HAK * 2));
#pragma unroll
            for (int nbp = 0; nbp < 4; nbp++) {
                uint32_t b4[4];
                ldsm_x4t(b4, bAddr + s * stageB + ks * (16 * HBN * 2) + nbp * 32);
#pragma unroll
                for (int mt = 0; mt < 4; mt++) {
                    mma_f16(acc[mt][2 * nbp],     afr[mt], b4[0], b4[1]);
                    mma_f16(acc[mt][2 * nbp + 1], afr[mt], b4[2], b4[3]);
                }
            }
        }
    }

#pragma unroll
    for (int mt = 0; mt < 4; mt++) {
        int r0 = m0 + wm * 64 + mt * 16 + g;
#pragma unroll
        for (int nt = 0; nt < 8; nt++) {
            int c0 = n0 + wn * 64 + nt * 8 + q * 2;
            if (HALF_OUT) {
                __half* C = (__half*)Cv;
                *(__half2*)&C[(size_t)r0 * N + c0] =
                    __floats2half2_rn(acc[mt][nt][0], acc[mt][nt][1]);
                *(__half2*)&C[(size_t)(r0 + 8) * N + c0] =
                    __floats2half2_rn(acc[mt][nt][2], acc[mt][nt][3]);
            } else {
                float* C = (float*)Cv;
                *(float2*)&C[(size_t)r0 * N + c0]       = make_float2(acc[mt][nt][0], acc[mt][nt][1]);
                *(float2*)&C[(size_t)(r0 + 8) * N + c0] = make_float2(acc[mt][nt][2], acc[mt][nt][3]);
            }
        }
    }
}

// ---------------------------------------------------------------------------
// Flash attention, fp16 mma + ldmatrix, triple-buffered cp.async K/V tiles.
// One CTA per (q-tile of 128 rows, b, h); big tiles first.
// ---------------------------------------------------------------------------
#define FST 72
#define NQT (SEQ/128)
#define KVST (2 * 64 * FST)   // halves per KV stage (K then V)
#define FLASH_SMEM ((128*FST + 3*KVST + 4*32*FST) * 2)

__global__ __launch_bounds__(128) void flash_f16(const __half* __restrict__ qkv,
                                                 __half* __restrict__ attn_out) {
    extern __shared__ __half smh[];
    __half* Qs = smh;                    // [qrow][d]
    __half* KV = Qs + 128 * FST;         // 3 stages of (K[64][FST], V[64][FST])
    __half* Ps = KV + 3 * KVST;          // [warp][row][key]

    const int tid  = threadIdx.x;
    const int lane = tid & 31;
    const int w    = tid >> 5;
    const int g    = lane >> 2;
    const int q    = lane & 3;

    const int bh = blockIdx.y;
    const int b  = bh >> 4;
    const int h  = bh & 15;

    const float LOG2E  = 1.44269504088896f;
    const float scale2 = 0.125f * LOG2E;
    const float slope2 = exp2f(-0.5f * (float)(h + 1)) * LOG2E;

    const __half* qb = qkv + (size_t)b * SEQ * (3 * DIM) + h * DH;
    const __half* kb = qb + DIM;
    const __half* vb = qb + 2 * DIM;

    __half* Pw = Ps + w * 32 * FST;

    const uint32_t sQ = smem_u32(Qs), sKV = smem_u32(KV), sP = smem_u32(Pw);
    const int l15 = lane & 15, lhi = lane >> 4;
    const uint32_t qA = sQ + (uint32_t)(((w * 32 + l15) * FST + lhi * 8) * 2);
    const uint32_t pA = sP + (uint32_t)((l15 * FST + lhi * 8) * 2);
    // relative (stage-0) ldmatrix B addresses
    const uint32_t kBr = sKV + (uint32_t)((((lane & 7) + ((lane >> 4) << 3)) * FST
                                          + ((lane >> 3) & 1) * 8) * 2);
    const uint32_t vBr = sKV + (uint32_t)(64 * FST * 2) +
                         (uint32_t)((l15 * FST + lhi * 8) * 2);

    const int qi = NQT - 1 - blockIdx.x;    // big tiles first
    const int q0 = qi * 128;

    // ---- load Q tile [128][64] (plain LDG/STS; covered by first barrier) ----
    {
        const __half* src = qb + (size_t)(q0 + tid) * (3 * DIM);
        __half* dst = Qs + tid * FST;
#pragma unroll
        for (int c = 0; c < 8; c++)
            *(uint4*)(dst + c * 8) = *(const uint4*)(src + c * 8);
    }

    // cp.async K/V tile loader: thread covers half a row of K and of V
    const int kvr = tid >> 1, kvc = (tid & 1) * 32;
    auto ld_kv = [&](int kt, int s) {
        const int k0_ = kt * 64;
        const __half* ksrc = kb + (size_t)(k0_ + kvr) * (3 * DIM) + kvc;
        const __half* vsrc = vb + (size_t)(k0_ + kvr) * (3 * DIM) + kvc;
        uint32_t kdst = sKV + (uint32_t)(s * KVST * 2) + (uint32_t)((kvr * FST + kvc) * 2);
        uint32_t vdst = kdst + (uint32_t)(64 * FST * 2);
#pragma unroll
        for (int j = 0; j < 4; j++) {
            CP_A16(kdst + j * 16, ksrc + j * 8);
            CP_A16(vdst + j * 16, vsrc + j * 8);
        }
    };

    float o[2][8][4];
    float mprev[2][2], lrun[2][2];
#pragma unroll
    for (int mt = 0; mt < 2; mt++) {
        mprev[mt][0] = mprev[mt][1] = -1e30f;
        lrun[mt][0]  = lrun[mt][1]  = 0.f;
#pragma unroll
        for (int nt = 0; nt < 8; nt++)
#pragma unroll
            for (int r = 0; r < 4; r++) o[mt][nt][r] = 0.f;
    }

    const int nkt = 2 * qi + 2;
    const int wrow_min = q0 + w * 32;
    const int wrow_max = wrow_min + 31;

    ld_kv(0, 0); CP_COMMIT();
    if (nkt > 1) { ld_kv(1, 1); CP_COMMIT(); }

    for (int kt = 0; kt < nkt; kt++) {
        const int s = kt % 3;
        const int k0 = kt * 64;
        if (kt + 1 < nkt) { CP_WAIT(1); } else { CP_WAIT(0); }
        __syncthreads();
        if (kt + 2 < nkt) { ld_kv(kt + 2, (kt + 2) % 3); CP_COMMIT(); }

        if (k0 > wrow_max) continue;

        const uint32_t kB = kBr + (uint32_t)(s * KVST * 2);
        const uint32_t vB = vBr + (uint32_t)(s * KVST * 2);

        // ---- S = Q @ K^T ----
        float sreg[2][8][4];
#pragma unroll
        for (int mt = 0; mt < 2; mt++)
#pragma unroll
            for (int nt = 0; nt < 8; nt++)
#pragma unroll
                for (int r = 0; r < 4; r++) sreg[mt][nt][r] = 0.f;

#pragma unroll
        for (int ks = 0; ks < 4; ks++) {
            uint32_t afr[2][4];
            ldsm_x4(afr[0], qA + ks * 32);
            ldsm_x4(afr[1], qA + ks * 32 + 16 * FST * 2);
#pragma unroll
            for (int nbp = 0; nbp < 4; nbp++) {
                uint32_t b4[4];
                ldsm_x4(b4, kB + nbp * 16 * FST * 2 + ks * 32);
                mma_f16(sreg[0][2 * nbp],     afr[0], b4[0], b4[1]);
                mma_f16(sreg[1][2 * nbp],     afr[1], b4[0], b4[1]);
                mma_f16(sreg[0][2 * nbp + 1], afr[0], b4[2], b4[3]);
                mma_f16(sreg[1][2 * nbp + 1], afr[1], b4[2], b4[3]);
            }
        }

        // ---- bias + mask + online softmax (base-2) ----
        const bool need_mask = (k0 + 63 > wrow_min);
#pragma unroll
        for (int mt = 0; mt < 2; mt++) {
            const int r0 = wrow_min + mt * 16 + g;
            const int r1 = r0 + 8;
            float mx0 = -1e30f, mx1 = -1e30f;
#pragma unroll
            for (int nt = 0; nt < 8; nt++) {
#pragma unroll
                for (int jj = 0; jj < 2; jj++) {
                    int col = k0 + nt * 8 + q * 2 + jj;
                    float bias = slope2 * (float)col;
                    float v0 = fmaf(sreg[mt][nt][jj],     scale2, bias);
                    float v1 = fmaf(sreg[mt][nt][2 + jj], scale2, bias);
                    if (need_mask) {
                        if (col > r0) v0 = -1e30f;
                        if (col > r1) v1 = -1e30f;
                    }
                    sreg[mt][nt][jj]     = v0;
                    sreg[mt][nt][2 + jj] = v1;
                    mx0 = fmaxf(mx0, v0);
                    mx1 = fmaxf(mx1, v1);
                }
            }
            mx0 = fmaxf(mx0, __shfl_xor_sync(0xffffffffu, mx0, 1));
            mx0 = fmaxf(mx0, __shfl_xor_sync(0xffffffffu, mx0, 2));
            mx1 = fmaxf(mx1, __shfl_xor_sync(0xffffffffu, mx1, 1));
            mx1 = fmaxf(mx1, __shfl_xor_sync(0xffffffffu, mx1, 2));

            float mn0 = fmaxf(mprev[mt][0], mx0);
            float mn1 = fmaxf(mprev[mt][1], mx1);
            float sum0 = 0.f, sum1 = 0.f;
#pragma unroll
            for (int nt = 0; nt < 8; nt++) {
#pragma unroll
                for (int jj = 0; jj < 2; jj++) {
                    float p0 = ex2f(sreg[mt][nt][jj]     - mn0);
                    float p1 = ex2f(sreg[mt][nt][2 + jj] - mn1);
                    sreg[mt][nt][jj]     = p0;
                    sreg[mt][nt][2 + jj] = p1;
                    sum0 += p0;
                    sum1 += p1;
                }
            }
            sum0 += __shfl_xor_sync(0xffffffffu, sum0, 1);
            sum0 += __shfl_xor_sync(0xffffffffu, sum0, 2);
            sum1 += __shfl_xor_sync(0xffffffffu, sum1, 1);
            sum1 += __shfl_xor_sync(0xffffffffu, sum1, 2);

            float al0 = ex2f(mprev[mt][0] - mn0);
            float al1 = ex2f(mprev[mt][1] - mn1);
            lrun[mt][0] = lrun[mt][0] * al0 + sum0;
            lrun[mt][1] = lrun[mt][1] * al1 + sum1;
            mprev[mt][0] = mn0;
            mprev[mt][1] = mn1;
#pragma unroll
            for (int nt = 0; nt < 8; nt++) {
                o[mt][nt][0] *= al0;
                o[mt][nt][1] *= al0;
                o[mt][nt][2] *= al1;
                o[mt][nt][3] *= al1;
            }

#pragma unroll
            for (int nt = 0; nt < 8; nt++) {
                *(__half2*)&Pw[(mt * 16 + g)     * FST + nt * 8 + q * 2] =
                    __floats2half2_rn(sreg[mt][nt][0], sreg[mt][nt][1]);
                *(__half2*)&Pw[(mt * 16 + g + 8) * FST + nt * 8 + q * 2] =
                    __floats2half2_rn(sreg[mt][nt][2], sreg[mt][nt][3]);
            }
        }
        __syncwarp();

        // ---- O += P @ V ----
#pragma unroll
        for (int ks = 0; ks < 4; ks++) {
            uint32_t afr[2][4];
            ldsm_x4(afr[0], pA + ks * 32);
            ldsm_x4(afr[1], pA + ks * 32 + 16 * FST * 2);
#pragma unroll
            for (int nbp = 0; nbp < 4; nbp++) {
                uint32_t b4[4];
                ldsm_x4t(b4, vB + ks * 16 * FST * 2 + nbp * 32);
                mma_f16(o[0][2 * nbp],     afr[0], b4[0], b4[1]);
                mma_f16(o[1][2 * nbp],     afr[1], b4[0], b4[1]);
                mma_f16(o[0][2 * nbp + 1], afr[0], b4[2], b4[3]);
                mma_f16(o[1][2 * nbp + 1], afr[1], b4[2], b4[3]);
            }
        }
    }

    // ---- epilogue ----
#pragma unroll
    for (int mt = 0; mt < 2; mt++) {
        float inv0 = 1.f / lrun[mt][0];
        float inv1 = 1.f / lrun[mt][1];
        int r0 = q0 + w * 32 + mt * 16 + g;
#pragma unroll
        for (int nt = 0; nt < 8; nt++) {
            int c = h * DH + nt * 8 + q * 2;
            *(__half2*)&attn_out[(size_t)(b * SEQ + r0) * DIM + c] =
                __floats2half2_rn(o[mt][nt][0] * inv0, o[mt][nt][1] * inv0);
            *(__half2*)&attn_out[(size_t)(b * SEQ + r0 + 8) * DIM + c] =
                __floats2half2_rn(o[mt][nt][2] * inv1, o[mt][nt][3] * inv1);
        }
    }
}

// ---------------------------------------------------------------------------
extern "C" void kernel_launch(void* const* d_in, const int* in_sizes, int n_in,
                              void* d_out, int out_size) {
    const float* x      = (const float*)d_in[0];
    const float* w_qkv  = (const float*)d_in[1];
    const float* w_proj = (const float*)d_in[2];
    float* out = (float*)d_out;

    __half *xh, *wqkvh, *wprojh, *qkv, *attn;
    cudaGetSymbolAddress((void**)&xh, g_xh);
    cudaGetSymbolAddress((void**)&wqkvh, g_wqkv_h);
    cudaGetSymbolAddress((void**)&wprojh, g_wproj_h);
    cudaGetSymbolAddress((void**)&qkv, g_qkv);
    cudaGetSymbolAddress((void**)&attn, g_attn);

    cudaFuncSetAttribute(flash_f16, cudaFuncAttributeMaxDynamicSharedMemorySize,
                         (int)FLASH_SMEM);

    // 0) convert inputs to half
    cvt_half_kernel<<<(MTOT * DIM) / 1024, 256>>>((const float4*)x, (uint2*)xh);
    cvt_half_kernel<<<(DIM * 3 * DIM) / 1024, 256>>>((const float4*)w_qkv, (uint2*)wqkvh);
    cvt_half_kernel<<<(DIM * DIM) / 1024, 256>>>((const float4*)w_proj, (uint2*)wprojh);

    // 1) qkv = x @ w_qkv  (half out)
    hgemm<true><<<dim3(3 * DIM / 128, MTOT / 128), 128>>>(xh, wqkvh, qkv, 3 * DIM, DIM);

    // 2) attention
    flash_f16<<<dim3(NQT, BATCH * HEADS), 128, FLASH_SMEM>>>(qkv, attn);

    // 3) out = attn @ w_proj  (float out)
    hgemm<false><<<dim3(DIM / 128, MTOT / 128), 128>>>(attn, wprojh, out, DIM, DIM);
}

// round 13
// speedup vs baseline: 2.2067x; 1.0624x over previous
#include <cuda_runtime.h>
#include <cuda_fp16.h>
#include <math.h>
#include <stdint.h>

// Problem constants
#define BATCH 2
#define SEQ   2048
#define DIM   1024
#define HEADS 16
#define DH    64
#define MTOT  (BATCH*SEQ)          // 4096 rows

// Scratch (allocation-free rule: __device__ globals)
__device__ __half g_xh[(size_t)MTOT * DIM];
__device__ __half g_wqkv_h[(size_t)DIM * 3 * DIM];
__device__ __half g_wproj_h[(size_t)DIM * DIM];
__device__ __half g_qkv[(size_t)MTOT * 3 * DIM];
__device__ __half g_attn[(size_t)MTOT * DIM];

// ---------------------------------------------------------------------------
// PTX helpers
// ---------------------------------------------------------------------------
__device__ __forceinline__ uint32_t smem_u32(const void* p) {
    uint32_t a;
    asm("{ .reg .u64 t; cvta.to.shared.u64 t, %1; cvt.u32.u64 %0, t; }" : "=r"(a) : "l"(p));
    return a;
}

__device__ __forceinline__ void ldsm_x4(uint32_t r[4], uint32_t addr) {
    asm volatile("ldmatrix.sync.aligned.m8n8.x4.shared.b16 {%0,%1,%2,%3}, [%4];"
                 : "=r"(r[0]), "=r"(r[1]), "=r"(r[2]), "=r"(r[3]) : "r"(addr));
}
__device__ __forceinline__ void ldsm_x4t(uint32_t r[4], uint32_t addr) {
    asm volatile("ldmatrix.sync.aligned.m8n8.x4.trans.shared.b16 {%0,%1,%2,%3}, [%4];"
                 : "=r"(r[0]), "=r"(r[1]), "=r"(r[2]), "=r"(r[3]) : "r"(addr));
}
__device__ __forceinline__ void mma_f16(float c[4], const uint32_t a[4],
                                        uint32_t b0, uint32_t b1) {
    asm volatile(
        "mma.sync.aligned.m16n8k16.row.col.f32.f16.f16.f32 "
        "{%0,%1,%2,%3}, {%4,%5,%6,%7}, {%8,%9}, {%0,%1,%2,%3};"
        : "+f"(c[0]), "+f"(c[1]), "+f"(c[2]), "+f"(c[3])
        : "r"(a[0]), "r"(a[1]), "r"(a[2]), "r"(a[3]), "r"(b0), "r"(b1));
}
__device__ __forceinline__ float ex2f(float x) {
    float r;
    asm("ex2.approx.ftz.f32 %0, %1;" : "=f"(r) : "f"(x));
    return r;
}

#define CP_A16(dst, src) \
    asm volatile("cp.async.cg.shared.global [%0], [%1], 16;" :: "r"(dst), "l"(src))
#define CP_COMMIT() asm volatile("cp.async.commit_group;" ::: "memory")
#define CP_WAIT(n)  asm volatile("cp.async.wait_group %0;" :: "n"(n) : "memory")

// ---------------------------------------------------------------------------
// fp32 -> fp16 conversion pre-pass
// ---------------------------------------------------------------------------
__global__ __launch_bounds__(256) void cvt_half_kernel(const float4* __restrict__ in,
                                                       uint2* __restrict__ out) {
    int i = blockIdx.x * 256 + threadIdx.x;
    float4 v = in[i];
    __half2 a = __floats2half2_rn(v.x, v.y);
    __half2 b = __floats2half2_rn(v.z, v.w);
    out[i] = make_uint2(*(uint32_t*)&a, *(uint32_t*)&b);
}

// ---------------------------------------------------------------------------
// FP16 tensor-core GEMM v4: 256 threads, 8 warps (2m x 4n), warp tile 64x32.
// Targets 2 CTAs/SM = 16 warps/SM for latency hiding.
// 3-stage cp.async pipeline, ldmatrix fragments.
// ---------------------------------------------------------------------------
#define HAK 40
#define HBN 136
#define NST 3

template <bool HALF_OUT>
__global__ __launch_bounds__(256, 2) void hgemm(const __half* __restrict__ A,
                                                const __half* __restrict__ B,
                                                void* __restrict__ Cv,
                                                int N, int K) {
    __shared__ __half As[NST][128][HAK];
    __shared__ __half Bs[NST][32][HBN];

    const int tid  = threadIdx.x;
    const int lane = tid & 31;
    const int wid  = tid >> 5;
    const int wm   = wid & 1;        // m offset wm*64
    const int wn   = wid >> 1;       // n offset wn*32 (0..3)
    const int g    = lane >> 2;
    const int q    = lane & 3;

    const int m0 = blockIdx.y * 128;
    const int n0 = blockIdx.x * 128;

    float acc[4][4][4];              // [mt 16-row][nt 8-col][frag]
#pragma unroll
    for (int i = 0; i < 4; i++)
#pragma unroll
        for (int j = 0; j < 4; j++)
#pragma unroll
            for (int r = 0; r < 4; r++) acc[i][j][r] = 0.f;

    const int NC = K / 32;

    const uint32_t aBase = smem_u32(&As[0][0][0]);
    const uint32_t bBase = smem_u32(&Bs[0][0][0]);
    const uint32_t stageA = 128 * HAK * 2;
    const uint32_t stageB = 32 * HBN * 2;

    const int l15 = lane & 15, lhi = lane >> 4;
    const uint32_t aAddr = aBase + (uint32_t)(((wm * 64 + l15) * HAK + lhi * 8) * 2);
    const uint32_t bAddr = bBase + (uint32_t)((l15 * HBN + wn * 32 + lhi * 8) * 2);

    // loaders: 256 threads
    const int arow = tid >> 1;                 // A row 0..127
    const int ach  = (tid & 1) * 16;           // A col halves 0/16
    const __half* Arow = A + (size_t)(m0 + arow) * K + ach;
    auto ld_async = [&](int c, int s) {
        const __half* asrc = Arow + c * 32;
        uint32_t adst = aBase + s * stageA + (uint32_t)((arow * HAK + ach) * 2);
        CP_A16(adst,      asrc);
        CP_A16(adst + 16, asrc + 8);
#pragma unroll
        for (int i = 0; i < 2; i++) {
            int idx = tid + i * 256;
            int row = idx >> 4, ch = idx & 15;
            const __half* bsrc = B + (size_t)(c * 32 + row) * N + n0 + ch * 8;
            uint32_t bdst = bBase + s * stageB + (uint32_t)((row * HBN + ch * 8) * 2);
            CP_A16(bdst, bsrc);
        }
    };

    ld_async(0, 0); CP_COMMIT();
    ld_async(1, 1); CP_COMMIT();

    for (int c = 0; c < NC; c++) {
        const int s = c % NST;
        if (c + 1 < NC) { CP_WAIT(1); } else { CP_WAIT(0); }
        __syncthreads();
        if (c + 2 < NC) { ld_async(c + 2, (c + 2) % NST); CP_COMMIT(); }

#pragma unroll
        for (int ks = 0; ks < 2; ks++) {
            uint32_t afr[4][4];
#pragma unroll
            for (int mt = 0; mt < 4; mt++)
                ldsm_x4(afr[mt], aAddr + s * stageA + ks * 32 + mt * (16 * HAK * 2));
#pragma unroll
            for (int nbp = 0; nbp < 2; nbp++) {
                uint32_t b4[4];
                ldsm_x4t(b4, bAddr + s * stageB + ks * (16 * HBN * 2) + nbp * 32);
#pragma unroll
                for (int mt = 0; mt < 4; mt++) {
                    mma_f16(acc[mt][2 * nbp],     afr[mt], b4[0], b4[1]);
                    mma_f16(acc[mt][2 * nbp + 1], afr[mt], b4[2], b4[3]);
                }
            }
        }
    }

    // epilogue: warp writes its 64x32 tile
#pragma unroll
    for (int mt = 0; mt < 4; mt++) {
        int r0 = m0 + wm * 64 + mt * 16 + g;
#pragma unroll
        for (int nt = 0; nt < 4; nt++) {
            int c0 = n0 + wn * 32 + nt * 8 + q * 2;
            if (HALF_OUT) {
                __half* C = (__half*)Cv;
                *(__half2*)&C[(size_t)r0 * N + c0] =
                    __floats2half2_rn(acc[mt][nt][0], acc[mt][nt][1]);
                *(__half2*)&C[(size_t)(r0 + 8) * N + c0] =
                    __floats2half2_rn(acc[mt][nt][2], acc[mt][nt][3]);
            } else {
                float* C = (float*)Cv;
                *(float2*)&C[(size_t)r0 * N + c0]       = make_float2(acc[mt][nt][0], acc[mt][nt][1]);
                *(float2*)&C[(size_t)(r0 + 8) * N + c0] = make_float2(acc[mt][nt][2], acc[mt][nt][3]);
            }
        }
    }
}

// ---------------------------------------------------------------------------
// Flash attention, fp16 mma + ldmatrix, triple-buffered cp.async K/V tiles.
// (unchanged from R11)
// ---------------------------------------------------------------------------
#define FST 72
#define NQT (SEQ/128)
#define KVST (2 * 64 * FST)   // halves per KV stage (K then V)
#define FLASH_SMEM ((128*FST + 3*KVST + 4*32*FST) * 2)

__global__ __launch_bounds__(128) void flash_f16(const __half* __restrict__ qkv,
                                                 __half* __restrict__ attn_out) {
    extern __shared__ __half smh[];
    __half* Qs = smh;
    __half* KV = Qs + 128 * FST;
    __half* Ps = KV + 3 * KVST;

    const int tid  = threadIdx.x;
    const int lane = tid & 31;
    const int w    = tid >> 5;
    const int g    = lane >> 2;
    const int q    = lane & 3;

    const int bh = blockIdx.y;
    const int b  = bh >> 4;
    const int h  = bh & 15;

    const float LOG2E  = 1.44269504088896f;
    const float scale2 = 0.125f * LOG2E;
    const float slope2 = exp2f(-0.5f * (float)(h + 1)) * LOG2E;

    const __half* qb = qkv + (size_t)b * SEQ * (3 * DIM) + h * DH;
    const __half* kb = qb + DIM;
    const __half* vb = qb + 2 * DIM;

    __half* Pw = Ps + w * 32 * FST;

    const uint32_t sQ = smem_u32(Qs), sKV = smem_u32(KV), sP = smem_u32(Pw);
    const int l15 = lane & 15, lhi = lane >> 4;
    const uint32_t qA = sQ + (uint32_t)(((w * 32 + l15) * FST + lhi * 8) * 2);
    const uint32_t pA = sP + (uint32_t)((l15 * FST + lhi * 8) * 2);
    const uint32_t kBr = sKV + (uint32_t)((((lane & 7) + ((lane >> 4) << 3)) * FST
                                          + ((lane >> 3) & 1) * 8) * 2);
    const uint32_t vBr = sKV + (uint32_t)(64 * FST * 2) +
                         (uint32_t)((l15 * FST + lhi * 8) * 2);

    const int qi = NQT - 1 - blockIdx.x;    // big tiles first
    const int q0 = qi * 128;

    {
        const __half* src = qb + (size_t)(q0 + tid) * (3 * DIM);
        __half* dst = Qs + tid * FST;
#pragma unroll
        for (int c = 0; c < 8; c++)
            *(uint4*)(dst + c * 8) = *(const uint4*)(src + c * 8);
    }

    const int kvr = tid >> 1, kvc = (tid & 1) * 32;
    auto ld_kv = [&](int kt, int s) {
        const int k0_ = kt * 64;
        const __half* ksrc = kb + (size_t)(k0_ + kvr) * (3 * DIM) + kvc;
        const __half* vsrc = vb + (size_t)(k0_ + kvr) * (3 * DIM) + kvc;
        uint32_t kdst = sKV + (uint32_t)(s * KVST * 2) + (uint32_t)((kvr * FST + kvc) * 2);
        uint32_t vdst = kdst + (uint32_t)(64 * FST * 2);
#pragma unroll
        for (int j = 0; j < 4; j++) {
            CP_A16(kdst + j * 16, ksrc + j * 8);
            CP_A16(vdst + j * 16, vsrc + j * 8);
        }
    };

    float o[2][8][4];
    float mprev[2][2], lrun[2][2];
#pragma unroll
    for (int mt = 0; mt < 2; mt++) {
        mprev[mt][0] = mprev[mt][1] = -1e30f;
        lrun[mt][0]  = lrun[mt][1]  = 0.f;
#pragma unroll
        for (int nt = 0; nt < 8; nt++)
#pragma unroll
            for (int r = 0; r < 4; r++) o[mt][nt][r] = 0.f;
    }

    const int nkt = 2 * qi + 2;
    const int wrow_min = q0 + w * 32;
    const int wrow_max = wrow_min + 31;

    ld_kv(0, 0); CP_COMMIT();
    if (nkt > 1) { ld_kv(1, 1); CP_COMMIT(); }

    for (int kt = 0; kt < nkt; kt++) {
        const int s = kt % 3;
        const int k0 = kt * 64;
        if (kt + 1 < nkt) { CP_WAIT(1); } else { CP_WAIT(0); }
        __syncthreads();
        if (kt + 2 < nkt) { ld_kv(kt + 2, (kt + 2) % 3); CP_COMMIT(); }

        if (k0 > wrow_max) continue;

        const uint32_t kB = kBr + (uint32_t)(s * KVST * 2);
        const uint32_t vB = vBr + (uint32_t)(s * KVST * 2);

        float sreg[2][8][4];
#pragma unroll
        for (int mt = 0; mt < 2; mt++)
#pragma unroll
            for (int nt = 0; nt < 8; nt++)
#pragma unroll
                for (int r = 0; r < 4; r++) sreg[mt][nt][r] = 0.f;

#pragma unroll
        for (int ks = 0; ks < 4; ks++) {
            uint32_t afr[2][4];
            ldsm_x4(afr[0], qA + ks * 32);
            ldsm_x4(afr[1], qA + ks * 32 + 16 * FST * 2);
#pragma unroll
            for (int nbp = 0; nbp < 4; nbp++) {
                uint32_t b4[4];
                ldsm_x4(b4, kB + nbp * 16 * FST * 2 + ks * 32);
                mma_f16(sreg[0][2 * nbp],     afr[0], b4[0], b4[1]);
                mma_f16(sreg[1][2 * nbp],     afr[1], b4[0], b4[1]);
                mma_f16(sreg[0][2 * nbp + 1], afr[0], b4[2], b4[3]);
                mma_f16(sreg[1][2 * nbp + 1], afr[1], b4[2], b4[3]);
            }
        }

        const bool need_mask = (k0 + 63 > wrow_min);
#pragma unroll
        for (int mt = 0; mt < 2; mt++) {
            const int r0 = wrow_min + mt * 16 + g;
            const int r1 = r0 + 8;
            float mx0 = -1e30f, mx1 = -1e30f;
#pragma unroll
            for (int nt = 0; nt < 8; nt++) {
#pragma unroll
                for (int jj = 0; jj < 2; jj++) {
                    int col = k0 + nt * 8 + q * 2 + jj;
                    float bias = slope2 * (float)col;
                    float v0 = fmaf(sreg[mt][nt][jj],     scale2, bias);
                    float v1 = fmaf(sreg[mt][nt][2 + jj], scale2, bias);
                    if (need_mask) {
                        if (col > r0) v0 = -1e30f;
                        if (col > r1) v1 = -1e30f;
                    }
                    sreg[mt][nt][jj]     = v0;
                    sreg[mt][nt][2 + jj] = v1;
                    mx0 = fmaxf(mx0, v0);
                    mx1 = fmaxf(mx1, v1);
                }
            }
            mx0 = fmaxf(mx0, __shfl_xor_sync(0xffffffffu, mx0, 1));
            mx0 = fmaxf(mx0, __shfl_xor_sync(0xffffffffu, mx0, 2));
            mx1 = fmaxf(mx1, __shfl_xor_sync(0xffffffffu, mx1, 1));
            mx1 = fmaxf(mx1, __shfl_xor_sync(0xffffffffu, mx1, 2));

            float mn0 = fmaxf(mprev[mt][0], mx0);
            float mn1 = fmaxf(mprev[mt][1], mx1);
            float sum0 = 0.f, sum1 = 0.f;
#pragma unroll
            for (int nt = 0; nt < 8; nt++) {
#pragma unroll
                for (int jj = 0; jj < 2; jj++) {
                    float p0 = ex2f(sreg[mt][nt][jj]     - mn0);
                    float p1 = ex2f(sreg[mt][nt][2 + jj] - mn1);
                    sreg[mt][nt][jj]     = p0;
                    sreg[mt][nt][2 + jj] = p1;
                    sum0 += p0;
                    sum1 += p1;
                }
            }
            sum0 += __shfl_xor_sync(0xffffffffu, sum0, 1);
            sum0 += __shfl_xor_sync(0xffffffffu, sum0, 2);
            sum1 += __shfl_xor_sync(0xffffffffu, sum1, 1);
            sum1 += __shfl_xor_sync(0xffffffffu, sum1, 2);

            float al0 = ex2f(mprev[mt][0] - mn0);
            float al1 = ex2f(mprev[mt][1] - mn1);
            lrun[mt][0] = lrun[mt][0] * al0 + sum0;
            lrun[mt][1] = lrun[mt][1] * al1 + sum1;
            mprev[mt][0] = mn0;
            mprev[mt][1] = mn1;
#pragma unroll
            for (int nt = 0; nt < 8; nt++) {
                o[mt][nt][0] *= al0;
                o[mt][nt][1] *= al0;
                o[mt][nt][2] *= al1;
                o[mt][nt][3] *= al1;
            }

#pragma unroll
            for (int nt = 0; nt < 8; nt++) {
                *(__half2*)&Pw[(mt * 16 + g)     * FST + nt * 8 + q * 2] =
                    __floats2half2_rn(sreg[mt][nt][0], sreg[mt][nt][1]);
                *(__half2*)&Pw[(mt * 16 + g + 8) * FST + nt * 8 + q * 2] =
                    __floats2half2_rn(sreg[mt][nt][2], sreg[mt][nt][3]);
            }
        }
        __syncwarp();

#pragma unroll
        for (int ks = 0; ks < 4; ks++) {
            uint32_t afr[2][4];
            ldsm_x4(afr[0], pA + ks * 32);
            ldsm_x4(afr[1], pA + ks * 32 + 16 * FST * 2);
#pragma unroll
            for (int nbp = 0; nbp < 4; nbp++) {
                uint32_t b4[4];
                ldsm_x4t(b4, vB + ks * 16 * FST * 2 + nbp * 32);
                mma_f16(o[0][2 * nbp],     afr[0], b4[0], b4[1]);
                mma_f16(o[1][2 * nbp],     afr[1], b4[0], b4[1]);
                mma_f16(o[0][2 * nbp + 1], afr[0], b4[2], b4[3]);
                mma_f16(o[1][2 * nbp + 1], afr[1], b4[2], b4[3]);
            }
        }
    }

#pragma unroll
    for (int mt = 0; mt < 2; mt++) {
        float inv0 = 1.f / lrun[mt][0];
        float inv1 = 1.f / lrun[mt][1];
        int r0 = q0 + w * 32 + mt * 16 + g;
#pragma unroll
        for (int nt = 0; nt < 8; nt++) {
            int c = h * DH + nt * 8 + q * 2;
            *(__half2*)&attn_out[(size_t)(b * SEQ + r0) * DIM + c] =
                __floats2half2_rn(o[mt][nt][0] * inv0, o[mt][nt][1] * inv0);
            *(__half2*)&attn_out[(size_t)(b * SEQ + r0 + 8) * DIM + c] =
                __floats2half2_rn(o[mt][nt][2] * inv1, o[mt][nt][3] * inv1);
        }
    }
}

// ---------------------------------------------------------------------------
extern "C" void kernel_launch(void* const* d_in, const int* in_sizes, int n_in,
                              void* d_out, int out_size) {
    const float* x      = (const float*)d_in[0];
    const float* w_qkv  = (const float*)d_in[1];
    const float* w_proj = (const float*)d_in[2];
    float* out = (float*)d_out;

    __half *xh, *wqkvh, *wprojh, *qkv, *attn;
    cudaGetSymbolAddress((void**)&xh, g_xh);
    cudaGetSymbolAddress((void**)&wqkvh, g_wqkv_h);
    cudaGetSymbolAddress((void**)&wprojh, g_wproj_h);
    cudaGetSymbolAddress((void**)&qkv, g_qkv);
    cudaGetSymbolAddress((void**)&attn, g_attn);

    cudaFuncSetAttribute(flash_f16, cudaFuncAttributeMaxDynamicSharedMemorySize,
                         (int)FLASH_SMEM);

    // 0) convert inputs to half
    cvt_half_kernel<<<(MTOT * DIM) / 1024, 256>>>((const float4*)x, (uint2*)xh);
    cvt_half_kernel<<<(DIM * 3 * DIM) / 1024, 256>>>((const float4*)w_qkv, (uint2*)wqkvh);
    cvt_half_kernel<<<(DIM * DIM) / 1024, 256>>>((const float4*)w_proj, (uint2*)wprojh);

    // 1) qkv = x @ w_qkv  (half out)
    hgemm<true><<<dim3(3 * DIM / 128, MTOT / 128), 256>>>(xh, wqkvh, qkv, 3 * DIM, DIM);

    // 2) attention
    flash_f16<<<dim3(NQT, BATCH * HEADS), 128, FLASH_SMEM>>>(qkv, attn);

    // 3) out = attn @ w_proj  (float out)
    hgemm<false><<<dim3(DIM / 128, MTOT / 128), 256>>>(attn, wprojh, out, DIM, DIM);
}